// round 1
// baseline (speedup 1.0000x reference)
#include <cuda_runtime.h>
#include <math.h>

#define NN 4096
#define NE 65536
#define D_IN 512
#define D_OUT 64

// ---------------- scratch layout (float offsets) ----------------
#define OFF_XL1F 0
#define OFF_XR1F 262144
#define OFF_XL1A 524288
#define OFF_XR1A 786432
#define OFF_E1   1048576   /* 2*65536 */
#define OFF_EMAX1 1179648  /* 2*4096 */
#define OFF_DEN1 1187840   /* 2*4096 */
#define OFF_AGG1 1196032   /* 2*4096*64 */
#define OFF_Z    1720320   /* 2*4096*64 */
#define OFF_EMB  2244608   /* 2*4096*64 */
#define OFF_XL2  2768896   /* 4096*512 */
#define OFF_XR2  4866048   /* 4096*512 */
#define OFF_E2   6963200   /* 65536 */
#define OFF_EMAX2 7028736  /* 4096 */
#define OFF_DEN2 7032832   /* 4096 */
#define OFF_AGG2 7036928   /* 4096*512 */
#define OFF_VS   9134080   /* 2*4096*64 */
#define OFF_RS   9658368   /* 4096 */
#define OFF_G    9662464   /* 2*4096*64 */
#define SCRATCH_N 10186752

__device__ float g_scratch[SCRATCH_N];

// ---------------- small utility kernels ----------------
__global__ void zero_kernel(float* p, int n) {
    int i = blockIdx.x * blockDim.x + threadIdx.x;
    int stride = gridDim.x * blockDim.x;
    float4* p4 = (float4*)p;
    int n4 = n >> 2;
    for (int j = i; j < n4; j += stride) p4[j] = make_float4(0.f, 0.f, 0.f, 0.f);
}

__global__ void fill_kernel(float* p, int n, float v) {
    int i = blockIdx.x * blockDim.x + threadIdx.x;
    if (i < n) p[i] = v;
}

__global__ void relu_kernel(const float* __restrict__ z, float* __restrict__ emb, int n) {
    int i = blockIdx.x * blockDim.x + threadIdx.x;
    if (i < n) emb[i] = fmaxf(z[i], 0.f);
}

__device__ __forceinline__ float sigmoidf(float x) { return 1.f / (1.f + __expf(-x)); }

__device__ __forceinline__ void atomicMaxF(float* addr, float val) {
    if (val >= 0.f) atomicMax((int*)addr, __float_as_int(val));
    else            atomicMin((unsigned int*)addr, __float_as_uint(val));
}

// ---------------- tiled SGEMM (row-major A[MxK] @ B[KxN] -> C[MxN]) ----------------
// gridDim.z = batch * nsplit. Split-K partials are atomicAdd'ed into pre-zeroed C.
template<int BM, int BN, int BK, int TM, int TN>
__global__ __launch_bounds__((BM/TM)*(BN/TN))
void sgemm(const float* __restrict__ A, int aStride,
           const float* __restrict__ B, int bStride,
           float* __restrict__ C, int cStride,
           int M, int N, int K, int kChunk, int nsplit)
{
    constexpr int THREADS = (BM/TM)*(BN/TN);
    __shared__ float As[BK][BM + 4];
    __shared__ float Bs[BK][BN];

    int batch = blockIdx.z / nsplit;
    int split = blockIdx.z % nsplit;
    A += (long)batch * aStride;
    B += (long)batch * bStride;
    C += (long)batch * cStride;
    int k0 = split * kChunk;
    int k1 = k0 + kChunk; if (k1 > K) k1 = K;

    int tid = threadIdx.x;
    int tx = tid % (BN / TN);
    int ty = tid / (BN / TN);
    int rowBase = blockIdx.x * BM;
    int colBase = blockIdx.y * BN;

    float acc[TM][TN];
    #pragma unroll
    for (int i = 0; i < TM; i++)
        #pragma unroll
        for (int j = 0; j < TN; j++) acc[i][j] = 0.f;

    for (int kt = k0; kt < k1; kt += BK) {
        #pragma unroll
        for (int i = 0; i < BM*BK/THREADS; i++) {
            int idx = tid + i * THREADS;
            int m = idx / BK, kk = idx % BK;
            As[kk][m] = A[(long)(rowBase + m) * K + kt + kk];
        }
        #pragma unroll
        for (int i = 0; i < BK*BN/THREADS; i++) {
            int idx = tid + i * THREADS;
            int kk = idx / BN, n = idx % BN;
            Bs[kk][n] = B[(long)(kt + kk) * N + colBase + n];
        }
        __syncthreads();
        #pragma unroll
        for (int kk = 0; kk < BK; kk++) {
            float ar[TM], br[TN];
            #pragma unroll
            for (int i = 0; i < TM; i++) ar[i] = As[kk][ty*TM + i];
            #pragma unroll
            for (int j = 0; j < TN; j++) br[j] = Bs[kk][tx*TN + j];
            #pragma unroll
            for (int i = 0; i < TM; i++)
                #pragma unroll
                for (int j = 0; j < TN; j++)
                    acc[i][j] = fmaf(ar[i], br[j], acc[i][j]);
        }
        __syncthreads();
    }

    if (nsplit > 1) {
        #pragma unroll
        for (int i = 0; i < TM; i++)
            #pragma unroll
            for (int j = 0; j < TN; j++)
                atomicAdd(&C[(long)(rowBase + ty*TM + i) * N + colBase + tx*TN + j], acc[i][j]);
    } else {
        #pragma unroll
        for (int i = 0; i < TM; i++)
            #pragma unroll
            for (int j = 0; j < TN; j++)
                C[(long)(rowBase + ty*TM + i) * N + colBase + tx*TN + j] = acc[i][j];
    }
}

// ---------------- GATv2 edge kernels ----------------
// pass 1: e_k = leakyrelu(xl[src]+xr[dst]) . att ; segment-max into emax[dst]
template<int D>
__global__ void edge_e(const float* __restrict__ xlB, const float* __restrict__ xrB,
                       const float* __restrict__ att,
                       const int* __restrict__ src, const int* __restrict__ dst,
                       float* eB, float* emaxB, int bsX, int bsE, int bsN)
{
    int b = blockIdx.y;
    const float* xl = xlB + (long)b * bsX;
    const float* xr = xrB + (long)b * bsX;
    float* e = eB + (long)b * bsE;
    float* emax = emaxB + (long)b * bsN;
    int warp = threadIdx.x >> 5, lane = threadIdx.x & 31;
    int k = blockIdx.x * 8 + warp;
    int s = src[k], d = dst[k];
    float sum = 0.f;
    #pragma unroll
    for (int i = 0; i < D/32; i++) {
        int idx = lane + i * 32;
        float v = xl[(long)s * D + idx] + xr[(long)d * D + idx];
        v = v > 0.f ? v : 0.2f * v;
        sum = fmaf(v, att[idx], sum);
    }
    #pragma unroll
    for (int o = 16; o; o >>= 1) sum += __shfl_xor_sync(0xffffffffu, sum, o);
    if (lane == 0) { e[k] = sum; atomicMaxF(&emax[d], sum); }
}

// pass 2: ee = exp(e - emax[dst]); den[dst] += ee (e overwritten with ee)
__global__ void edge_sm(float* eB, const float* __restrict__ emaxB, float* denB,
                        const int* __restrict__ dst, int bsE, int bsN)
{
    int b = blockIdx.y;
    float* e = eB + (long)b * bsE;
    const float* emax = emaxB + (long)b * bsN;
    float* den = denB + (long)b * bsN;
    int k = blockIdx.x * blockDim.x + threadIdx.x;
    int d = dst[k];
    float ee = __expf(e[k] - emax[d]);
    e[k] = ee;
    atomicAdd(&den[d], ee);
}

// pass 3: agg[dst] += (ee/den[dst]) * xl[src]
template<int D>
__global__ void edge_agg(const float* __restrict__ eB, const float* __restrict__ denB,
                         const float* __restrict__ xlB,
                         const int* __restrict__ src, const int* __restrict__ dst,
                         float* aggB, int bsX, int bsE, int bsN, int bsAgg)
{
    int b = blockIdx.y;
    const float* e = eB + (long)b * bsE;
    const float* den = denB + (long)b * bsN;
    const float* xl = xlB + (long)b * bsX;
    float* agg = aggB + (long)b * bsAgg;
    int warp = threadIdx.x >> 5, lane = threadIdx.x & 31;
    int k = blockIdx.x * 8 + warp;
    int s = src[k], d = dst[k];
    float dn = den[d];
    float alpha = e[k] / (dn == 0.f ? 1.f : dn);
    #pragma unroll
    for (int i = 0; i < D/32; i++) {
        int idx = lane + i * 32;
        atomicAdd(&agg[(long)d * D + idx], alpha * xl[(long)s * D + idx]);
    }
}

// ---------------- readout ----------------
__global__ void rowsum_kernel(const float* __restrict__ gnm, float* rs)
{
    int warp = threadIdx.x >> 5, lane = threadIdx.x & 31;
    int row = blockIdx.x * 8 + warp;
    const float4* p = (const float4*)(gnm + (long)row * NN);
    float s = 0.f;
    for (int i = lane; i < NN/4; i += 32) { float4 v = p[i]; s += (v.x + v.y) + (v.z + v.w); }
    #pragma unroll
    for (int o = 16; o; o >>= 1) s += __shfl_xor_sync(0xffffffffu, s, o);
    if (lane == 0) rs[row] = s;
}

__global__ void readout_g(const float* vsB, const float* __restrict__ rs, float* gB, int bs)
{
    int b = blockIdx.y;
    const float* vs = vsB + (long)b * bs;
    float* g = gB + (long)b * bs;
    int warp = threadIdx.x >> 5, lane = threadIdx.x & 31;
    int n = blockIdx.x * 8 + warp;
    float inv = 1.f / rs[n];
    float v0 = vs[n*64 + lane] * inv;
    float v1 = vs[n*64 + lane + 32] * inv;
    float ss = v0*v0 + v1*v1;
    #pragma unroll
    for (int o = 16; o; o >>= 1) ss += __shfl_xor_sync(0xffffffffu, ss, o);
    float nrm = fmaxf(sqrtf(ss), 1e-12f);
    g[n*64 + lane]      = sigmoidf(v0 / nrm);
    g[n*64 + lane + 32] = sigmoidf(v1 / nrm);
}

// ---------------- bilinear discriminator ----------------
__global__ void bilinear_kernel(const float* __restrict__ emb, const float* __restrict__ emba,
                                const float* __restrict__ gf,  const float* __restrict__ ga,
                                const float* __restrict__ Wb,  const float* __restrict__ bb,
                                float* ret, float* reta)
{
    __shared__ float sW[64 * 65];
    __shared__ float sg[8][64];
    __shared__ float sga[8][64];
    for (int i = threadIdx.x; i < 64*64; i += blockDim.x)
        sW[(i >> 6) * 65 + (i & 63)] = Wb[i];
    int warp = threadIdx.x >> 5, lane = threadIdx.x & 31;
    int n = blockIdx.x * 8 + warp;
    sg[warp][lane]       = gf[n*64 + lane];
    sg[warp][lane + 32]  = gf[n*64 + lane + 32];
    sga[warp][lane]      = ga[n*64 + lane];
    sga[warp][lane + 32] = ga[n*64 + lane + 32];
    __syncthreads();

    float wcf0 = 0.f, wcf1 = 0.f, wca0 = 0.f, wca1 = 0.f;
    #pragma unroll 8
    for (int k2 = 0; k2 < 64; k2++) {
        float w0 = sW[lane * 65 + k2];
        float w1 = sW[(lane + 32) * 65 + k2];
        float gv = sg[warp][k2];
        float gav = sga[warp][k2];
        wcf0 = fmaf(w0, gv,  wcf0); wcf1 = fmaf(w1, gv,  wcf1);
        wca0 = fmaf(w0, gav, wca0); wca1 = fmaf(w1, gav, wca1);
    }
    float e0 = emb[n*64 + lane],  e1 = emb[n*64 + lane + 32];
    float a0 = emba[n*64 + lane], a1 = emba[n*64 + lane + 32];
    float d1 = e0*wcf0 + e1*wcf1;   // bil(emb,   g)
    float d2 = a0*wcf0 + a1*wcf1;   // bil(emb_a, g)
    float d3 = a0*wca0 + a1*wca1;   // bil(emb_a, g_a)
    float d4 = e0*wca0 + e1*wca1;   // bil(emb,   g_a)
    #pragma unroll
    for (int o = 16; o; o >>= 1) {
        d1 += __shfl_xor_sync(0xffffffffu, d1, o);
        d2 += __shfl_xor_sync(0xffffffffu, d2, o);
        d3 += __shfl_xor_sync(0xffffffffu, d3, o);
        d4 += __shfl_xor_sync(0xffffffffu, d4, o);
    }
    if (lane == 0) {
        float bias = bb[0];
        ret[n*2 + 0]  = sigmoidf(d1 + bias);
        ret[n*2 + 1]  = sigmoidf(d2 + bias);
        reta[n*2 + 0] = sigmoidf(d3 + bias);
        reta[n*2 + 1] = sigmoidf(d4 + bias);
    }
}

// ---------------- launch ----------------
extern "C" void kernel_launch(void* const* d_in, const int* in_sizes, int n_in,
                              void* d_out, int out_size)
{
    const float* feat  = (const float*)d_in[0];
    const float* feata = (const float*)d_in[1];
    const float* adj   = (const float*)d_in[2];
    const float* gn    = (const float*)d_in[3];
    const float* Wl1   = (const float*)d_in[4];
    const float* Wr1   = (const float*)d_in[5];
    const float* att1  = (const float*)d_in[6];
    const float* Wl2   = (const float*)d_in[7];
    const float* Wr2   = (const float*)d_in[8];
    const float* att2  = (const float*)d_in[9];
    const float* Wb    = (const float*)d_in[10];
    const float* bb    = (const float*)d_in[11];
    const int*   src   = (const int*)d_in[12];
    const int*   dst   = (const int*)d_in[13];
    float* out = (float*)d_out;

    float* sc = nullptr;
    cudaGetSymbolAddress((void**)&sc, g_scratch);

    // init: zero scratch, set segment-max buffers to -inf
    zero_kernel<<<2048, 256>>>(sc, SCRATCH_N);
    fill_kernel<<<32, 256>>>(sc + OFF_EMAX1, 8192, -INFINITY);
    fill_kernel<<<16, 256>>>(sc + OFF_EMAX2, 4096, -INFINITY);

    // stage 1: xl/xr = {feat,feat_a} @ {Wl1,Wr1}  (M=4096,N=64,K=512; split-K=4)
    dim3 g1(32, 1, 4);
    sgemm<128,64,8,8,4><<<g1, 256>>>(feat,  0, Wl1, 0, sc + OFF_XL1F, 0, NN, 64, 512, 128, 4);
    sgemm<128,64,8,8,4><<<g1, 256>>>(feat,  0, Wr1, 0, sc + OFF_XR1F, 0, NN, 64, 512, 128, 4);
    sgemm<128,64,8,8,4><<<g1, 256>>>(feata, 0, Wl1, 0, sc + OFF_XL1A, 0, NN, 64, 512, 128, 4);
    sgemm<128,64,8,8,4><<<g1, 256>>>(feata, 0, Wr1, 0, sc + OFF_XR1A, 0, NN, 64, 512, 128, 4);

    // GAT layer 1 (batched over feat / feat_a)
    edge_e<64><<<dim3(NE/8, 2), 256>>>(sc+OFF_XL1F, sc+OFF_XR1F, att1, src, dst,
                                       sc+OFF_E1, sc+OFF_EMAX1, 524288, 65536, 4096);
    edge_sm<<<dim3(NE/256, 2), 256>>>(sc+OFF_E1, sc+OFF_EMAX1, sc+OFF_DEN1, dst, 65536, 4096);
    edge_agg<64><<<dim3(NE/8, 2), 256>>>(sc+OFF_E1, sc+OFF_DEN1, sc+OFF_XL1F, src, dst,
                                         sc+OFF_AGG1, 524288, 65536, 4096, 262144);

    // z/z_a = adj @ agg1  (M=4096,N=64,K=4096; batch=2, split-K=4)
    sgemm<128,64,8,8,4><<<dim3(32, 1, 8), 256>>>(adj, 0, sc+OFF_AGG1, 262144,
                                                 sc+OFF_Z, 262144, NN, 64, NN, 1024, 4);
    // hiden_emb = z
    cudaMemcpyAsync(out, sc + OFF_Z, 262144 * sizeof(float), cudaMemcpyDeviceToDevice);
    // emb = relu(z), emb_a = relu(z_a)
    relu_kernel<<<524288/256, 256>>>(sc + OFF_Z, sc + OFF_EMB, 524288);

    // stage 2 transforms: xl2/xr2 = z @ {Wl2,Wr2}  (M=4096,N=512,K=64)
    sgemm<128,128,8,8,8><<<dim3(32, 4, 1), 256>>>(sc+OFF_Z, 0, Wl2, 0, sc+OFF_XL2, 0, NN, 512, 64, 64, 1);
    sgemm<128,128,8,8,8><<<dim3(32, 4, 1), 256>>>(sc+OFF_Z, 0, Wr2, 0, sc+OFF_XR2, 0, NN, 512, 64, 64, 1);

    // GAT layer 2
    edge_e<512><<<dim3(NE/8, 1), 256>>>(sc+OFF_XL2, sc+OFF_XR2, att2, src, dst,
                                        sc+OFF_E2, sc+OFF_EMAX2, 0, 0, 0);
    edge_sm<<<dim3(NE/256, 1), 256>>>(sc+OFF_E2, sc+OFF_EMAX2, sc+OFF_DEN2, dst, 0, 0);
    edge_agg<512><<<dim3(NE/8, 1), 256>>>(sc+OFF_E2, sc+OFF_DEN2, sc+OFF_XL2, src, dst,
                                          sc+OFF_AGG2, 0, 0, 0, 0);

    // h = adj @ agg2  (M=4096,N=512,K=4096) -> directly into output
    sgemm<128,128,8,8,8><<<dim3(32, 4, 1), 256>>>(adj, 0, sc+OFF_AGG2, 0,
                                                  out + 262144, 0, NN, 512, NN, 4096, 1);

    // readout: vs = gn @ {emb, emb_a}  (batch=2, split-K=4)
    sgemm<128,64,8,8,4><<<dim3(32, 1, 8), 256>>>(gn, 0, sc+OFF_EMB, 262144,
                                                 sc+OFF_VS, 262144, NN, 64, NN, 1024, 4);
    rowsum_kernel<<<512, 256>>>(gn, sc + OFF_RS);
    readout_g<<<dim3(512, 2), 256>>>(sc+OFF_VS, sc+OFF_RS, sc+OFF_G, 262144);

    // bilinear discriminator -> ret, ret_a
    bilinear_kernel<<<512, 256>>>(sc+OFF_EMB, sc+OFF_EMB + 262144,
                                  sc+OFF_G,   sc+OFF_G + 262144,
                                  Wb, bb, out + 2359296, out + 2367488);
}

// round 4
// speedup vs baseline: 1.8883x; 1.8883x over previous
#include <cuda_runtime.h>
#include <cuda_bf16.h>
#include <cstdint>
#include <math.h>

#define NN 4096
#define NE 65536

// ================= float scratch (element offsets) =================
#define OFF_X1    0u          /* [2][4096][128] xl|xr */
#define OFF_Z     1048576u    /* [4096][128] z|z_a */
#define OFF_EMB   1572864u    /* [4096][128] emb|emb_a */
#define OFF_X2    2097152u    /* [4096][1024] xl2|xr2 */
#define OFF_AGG1  6291456u    /* [2][4096][64] */
#define OFF_AGG2  6815744u    /* [4096][512] */
#define OFF_VS    8912896u    /* [4096][128] vs|vs_a */
#define OFF_E1    9437184u    /* [2][65536] */
#define OFF_EMAX1 9568256u
#define OFF_DEN1  9576448u
#define OFF_E2    9584640u
#define OFF_EMAX2 9650176u
#define OFF_DEN2  9654272u
#define OFF_G     9658368u    /* [2][4096][64] */
#define OFF_RS    10182656u
#define FSCRATCH_N 10186752u
__device__ __align__(16) float g_fscratch[FSCRATCH_N];

// ================= bf16 scratch =================
#define B_ADJ_HI  0u
#define B_ADJ_LO  16777216u
#define B_GN_HI   33554432u
#define B_GN_LO   50331648u
#define B_FEAT_HI 67108864u   /* [2][4096][512] */
#define B_FEAT_LO 71303168u
#define B_W1T_HI  75497472u   /* [128][512] */
#define B_W1T_LO  75563008u
#define B_W2T_HI  75628544u   /* [1024][64] */
#define B_W2T_LO  75694080u
#define B_Z_HI    75759616u   /* [4096][128] */
#define B_Z_LO    76283904u
#define B_A1T_HI  76808192u   /* [128][4096] */
#define B_A1T_LO  77332480u
#define B_EMBT_HI 77856768u   /* [128][4096] */
#define B_EMBT_LO 78381056u
#define B_A2T_HI  78905344u   /* [512][4096] */
#define B_A2T_LO  81002496u
#define BSCRATCH_N 83099648u
__device__ __align__(16) __nv_bfloat16 g_bscratch[BSCRATCH_N];

// ================= warp-MMA helpers (sm_80+ ISA, works on plain sm_100) ====
__device__ __forceinline__ uint32_t smem_u32(const void* p) {
    uint32_t a;
    asm("{ .reg .u64 t; cvta.to.shared.u64 t, %1; cvt.u32.u64 %0, t; }" : "=r"(a) : "l"(p));
    return a;
}
__device__ __forceinline__ void cp_async16(uint32_t saddr, const void* gaddr) {
    asm volatile("cp.async.cg.shared.global [%0], [%1], 16;" :: "r"(saddr), "l"(gaddr));
}
#define CP_COMMIT() asm volatile("cp.async.commit_group;" ::: "memory")
#define CP_WAIT(N)  asm volatile("cp.async.wait_group %0;" :: "n"(N) : "memory")

__device__ __forceinline__ void ldsm4(uint32_t* r, uint32_t addr) {
    asm volatile("ldmatrix.sync.aligned.m8n8.x4.shared.b16 {%0,%1,%2,%3}, [%4];"
        : "=r"(r[0]), "=r"(r[1]), "=r"(r[2]), "=r"(r[3]) : "r"(addr));
}
__device__ __forceinline__ void mma16816(float* d, const uint32_t* a, uint32_t b0, uint32_t b1) {
    asm volatile("mma.sync.aligned.m16n8k16.row.col.f32.bf16.bf16.f32 "
        "{%0,%1,%2,%3}, {%4,%5,%6,%7}, {%8,%9}, {%0,%1,%2,%3};"
        : "+f"(d[0]), "+f"(d[1]), "+f"(d[2]), "+f"(d[3])
        : "r"(a[0]), "r"(a[1]), "r"(a[2]), "r"(a[3]), "r"(b0), "r"(b1));
}

// ============ mma GEMM: C[M,N]fp32 = A[M,K] @ Bt[N,K]^T, bf16 hi/lo 3-phase ====
// 128x128 tile, BK=32, 256 threads (8 warps, 4x2), cp.async double buffer.
// smem rows padded to 80B -> (5r+c) mod 8 quad pattern, conflict-free ldmatrix.
#define STG 20480
__global__ __launch_bounds__(256) void mma_gemm(
    const __nv_bfloat16* __restrict__ Ahi, const __nv_bfloat16* __restrict__ Alo, int lda,
    const __nv_bfloat16* __restrict__ Bthi, const __nv_bfloat16* __restrict__ Btlo, int ldb,
    float* __restrict__ C, int ldC, int K,
    int nsplit, int kPerSplit, long aBS, long cBS, int doAtomic)
{
    __shared__ __align__(16) char sm[2 * STG];
    int tid = threadIdx.x, lane = tid & 31, wid = tid >> 5;
    int warpM = wid & 3, warpN = wid >> 2;
    int m0 = blockIdx.x * 128, n0 = blockIdx.y * 128;
    int batch = blockIdx.z / nsplit, split = blockIdx.z % nsplit;
    int kBeg = split * kPerSplit;
    int kEnd = kBeg + kPerSplit; if (kEnd > K) kEnd = K;
    int nk = (kEnd - kBeg) >> 5;
    int NIT = 3 * nk;
    const __nv_bfloat16* Abh = Ahi + (size_t)batch * aBS;
    const __nv_bfloat16* Abl = Alo + (size_t)batch * aBS;
    float* Cb = C + (size_t)batch * cBS;
    uint32_t smBase = smem_u32(sm);

    float acc[2][8][4];
    #pragma unroll
    for (int t = 0; t < 2; t++)
        #pragma unroll
        for (int n = 0; n < 8; n++)
            #pragma unroll
            for (int j = 0; j < 4; j++) acc[t][n][j] = 0.f;

    int r0i = tid >> 2, c0i = tid & 3;            // chunk 0: idx=tid
    int r1i = (tid + 256) >> 2, c1i = tid & 3;    // chunk 1: idx=tid+256

    auto load_stage = [&](int s, int it) {
        int p = it / nk;
        int kt = kBeg + ((it - p * nk) << 5);
        const __nv_bfloat16* Ap = (p == 1) ? Abl : Abh;
        const __nv_bfloat16* Bp = (p == 2) ? Btlo : Bthi;
        uint32_t sa = smBase + s * STG;
        uint32_t sb = sa + 10240;
        cp_async16(sa + r0i * 80 + c0i * 16, Ap + (size_t)(m0 + r0i) * lda + kt + c0i * 8);
        cp_async16(sa + r1i * 80 + c1i * 16, Ap + (size_t)(m0 + r1i) * lda + kt + c1i * 8);
        cp_async16(sb + r0i * 80 + c0i * 16, Bp + (size_t)(n0 + r0i) * ldb + kt + c0i * 8);
        cp_async16(sb + r1i * 80 + c1i * 16, Bp + (size_t)(n0 + r1i) * ldb + kt + c1i * 8);
        CP_COMMIT();
    };

    load_stage(0, 0);
    int lrow = (lane & 7) + ((lane >> 3) & 1) * 8;
    int lkHalf = (lane >> 4);  // 0/1 -> k-halves

    for (int it = 0; it < NIT; ++it) {
        if (it + 1 < NIT) { load_stage((it + 1) & 1, it + 1); CP_WAIT(1); }
        else              { CP_WAIT(0); }
        __syncthreads();
        uint32_t sa = smBase + (it & 1) * STG;
        uint32_t sb = sa + 10240;
        #pragma unroll
        for (int ks = 0; ks < 2; ks++) {
            int chunk = ks * 2 + lkHalf;
            uint32_t aF[2][4], bF[4][4];
            #pragma unroll
            for (int t = 0; t < 2; t++)
                ldsm4(aF[t], sa + (uint32_t)(warpM * 32 + t * 16 + lrow) * 80 + chunk * 16);
            #pragma unroll
            for (int pp = 0; pp < 4; pp++)
                ldsm4(bF[pp], sb + (uint32_t)(warpN * 64 + pp * 16 + lrow) * 80 + chunk * 16);
            #pragma unroll
            for (int t = 0; t < 2; t++)
                #pragma unroll
                for (int nt = 0; nt < 8; nt++)
                    mma16816(acc[t][nt], aF[t], bF[nt >> 1][nt & 1], bF[nt >> 1][2 + (nt & 1)]);
        }
        __syncthreads();
    }

    int g = lane >> 2, q = lane & 3;
    #pragma unroll
    for (int t = 0; t < 2; t++) {
        #pragma unroll
        for (int nt = 0; nt < 8; nt++) {
            int row = m0 + warpM * 32 + t * 16 + g;
            int col = n0 + warpN * 64 + nt * 8 + q * 2;
            float* p0 = Cb + (size_t)row * ldC + col;
            float* p1 = Cb + (size_t)(row + 8) * ldC + col;
            if (doAtomic) {
                atomicAdd(p0,     acc[t][nt][0]); atomicAdd(p0 + 1, acc[t][nt][1]);
                atomicAdd(p1,     acc[t][nt][2]); atomicAdd(p1 + 1, acc[t][nt][3]);
            } else {
                *(float2*)p0 = make_float2(acc[t][nt][0], acc[t][nt][1]);
                *(float2*)p1 = make_float2(acc[t][nt][2], acc[t][nt][3]);
            }
        }
    }
}

// ================= conversions =================
__global__ void rconv(const float* __restrict__ src, __nv_bfloat16* __restrict__ hi,
                      __nv_bfloat16* __restrict__ lo, int n2)
{
    int i = blockIdx.x * blockDim.x + threadIdx.x;
    if (i >= n2) return;
    float2 f = ((const float2*)src)[i];
    __nv_bfloat16 h0 = __float2bfloat16_rn(f.x);
    __nv_bfloat16 h1 = __float2bfloat16_rn(f.y);
    __nv_bfloat16 l0 = __float2bfloat16_rn(f.x - __bfloat162float(h0));
    __nv_bfloat16 l1 = __float2bfloat16_rn(f.y - __bfloat162float(h1));
    ((__nv_bfloat162*)hi)[i] = __halves2bfloat162(h0, h1);
    ((__nv_bfloat162*)lo)[i] = __halves2bfloat162(l0, l1);
}

// transpose+convert: src fp32 (ldSrc) -> dst bf16 [(col+rowOff)][row] (ldDst)
__global__ void tconv(const float* __restrict__ src, int ldSrc,
                      __nv_bfloat16* __restrict__ dhi, __nv_bfloat16* __restrict__ dlo,
                      int ldDst, int rowOff)
{
    __shared__ float t[32][33];
    int rb = blockIdx.y * 32, cb = blockIdx.x * 32;
    int tx = threadIdx.x, ty = threadIdx.y;
    #pragma unroll
    for (int i = 0; i < 4; i++)
        t[ty + 8 * i][tx] = src[(size_t)(rb + ty + 8 * i) * ldSrc + cb + tx];
    __syncthreads();
    #pragma unroll
    for (int i = 0; i < 4; i++) {
        int c = cb + ty + 8 * i;
        float v = t[tx][ty + 8 * i];
        __nv_bfloat16 h = __float2bfloat16_rn(v);
        size_t o = (size_t)(c + rowOff) * ldDst + rb + tx;
        dhi[o] = h;
        dlo[o] = __float2bfloat16_rn(v - __bfloat162float(h));
    }
}

// ================= utility =================
__global__ void zero_kernel(float* p, int n) {
    int i = blockIdx.x * blockDim.x + threadIdx.x;
    int stride = gridDim.x * blockDim.x;
    float4* p4 = (float4*)p;
    int n4 = n >> 2;
    for (int j = i; j < n4; j += stride) p4[j] = make_float4(0.f, 0.f, 0.f, 0.f);
}
__global__ void fill_kernel(float* p, int n, float v) {
    int i = blockIdx.x * blockDim.x + threadIdx.x;
    if (i < n) p[i] = v;
}
__global__ void relu_kernel(const float* __restrict__ z, float* __restrict__ emb, int n) {
    int i = blockIdx.x * blockDim.x + threadIdx.x;
    if (i < n) emb[i] = fmaxf(z[i], 0.f);
}
__global__ void copy_z_kernel(const float* __restrict__ Z, float* __restrict__ out) {
    int i = blockIdx.x * blockDim.x + threadIdx.x;  // 262144
    int n = i >> 6, c = i & 63;
    out[i] = Z[n * 128 + c];
}
__device__ __forceinline__ float sigmoidf_(float x) { return 1.f / (1.f + __expf(-x)); }
__device__ __forceinline__ void atomicMaxF(float* a, float v) {
    if (v >= 0.f) atomicMax((int*)a, __float_as_int(v));
    else          atomicMin((unsigned int*)a, __float_as_uint(v));
}

// ================= GATv2 edge kernels =================
template<int D>
__global__ void edge_e(const float* __restrict__ xlB, const float* __restrict__ xrB, int ldx,
                       const float* __restrict__ att,
                       const int* __restrict__ src, const int* __restrict__ dst,
                       float* eB, float* emaxB, int bsX, int bsE, int bsN)
{
    int b = blockIdx.y;
    const float* xl = xlB + (long)b * bsX;
    const float* xr = xrB + (long)b * bsX;
    float* e = eB + (long)b * bsE;
    float* emax = emaxB + (long)b * bsN;
    int warp = threadIdx.x >> 5, lane = threadIdx.x & 31;
    int k = blockIdx.x * 8 + warp;
    int s = src[k], d = dst[k];
    float sum = 0.f;
    #pragma unroll
    for (int i = 0; i < D / 32; i++) {
        int idx = lane + i * 32;
        float v = xl[(size_t)s * ldx + idx] + xr[(size_t)d * ldx + idx];
        v = v > 0.f ? v : 0.2f * v;
        sum = fmaf(v, att[idx], sum);
    }
    #pragma unroll
    for (int o = 16; o; o >>= 1) sum += __shfl_xor_sync(0xffffffffu, sum, o);
    if (lane == 0) { e[k] = sum; atomicMaxF(&emax[d], sum); }
}

__global__ void edge_sm(float* eB, const float* __restrict__ emaxB, float* denB,
                        const int* __restrict__ dst, int bsE, int bsN)
{
    int b = blockIdx.y;
    float* e = eB + (long)b * bsE;
    const float* emax = emaxB + (long)b * bsN;
    float* den = denB + (long)b * bsN;
    int k = blockIdx.x * blockDim.x + threadIdx.x;
    int d = dst[k];
    float ee = __expf(e[k] - emax[d]);
    e[k] = ee;
    atomicAdd(&den[d], ee);
}

template<int D>
__global__ void edge_agg(const float* __restrict__ eB, const float* __restrict__ denB,
                         const float* __restrict__ xlB, int ldx,
                         const int* __restrict__ src, const int* __restrict__ dst,
                         float* aggB, int bsX, int bsE, int bsN, int bsAgg)
{
    int b = blockIdx.y;
    const float* e = eB + (long)b * bsE;
    const float* den = denB + (long)b * bsN;
    const float* xl = xlB + (long)b * bsX;
    float* agg = aggB + (long)b * bsAgg;
    int warp = threadIdx.x >> 5, lane = threadIdx.x & 31;
    int k = blockIdx.x * 8 + warp;
    int s = src[k], d = dst[k];
    float dn = den[d];
    float alpha = e[k] / (dn == 0.f ? 1.f : dn);
    #pragma unroll
    for (int i = 0; i < D / 32; i++) {
        int idx = lane + i * 32;
        atomicAdd(&agg[(size_t)d * D + idx], alpha * xl[(size_t)s * ldx + idx]);
    }
}

// ================= readout =================
__global__ void rowsum_kernel(const float* __restrict__ gnm, float* rs)
{
    int warp = threadIdx.x >> 5, lane = threadIdx.x & 31;
    int row = blockIdx.x * 8 + warp;
    const float4* p = (const float4*)(gnm + (size_t)row * NN);
    float s = 0.f;
    for (int i = lane; i < NN / 4; i += 32) { float4 v = p[i]; s += (v.x + v.y) + (v.z + v.w); }
    #pragma unroll
    for (int o = 16; o; o >>= 1) s += __shfl_xor_sync(0xffffffffu, s, o);
    if (lane == 0) rs[row] = s;
}

__global__ void readout_g(const float* __restrict__ VS, const float* __restrict__ rs,
                          float* __restrict__ G)
{
    int b = blockIdx.y;
    int warp = threadIdx.x >> 5, lane = threadIdx.x & 31;
    int n = blockIdx.x * 8 + warp;
    const float* vs = VS + (size_t)n * 128 + b * 64;
    float* g = G + (size_t)b * 262144 + (size_t)n * 64;
    float inv = 1.f / rs[n];
    float v0 = vs[lane] * inv;
    float v1 = vs[lane + 32] * inv;
    float ss = v0 * v0 + v1 * v1;
    #pragma unroll
    for (int o = 16; o; o >>= 1) ss += __shfl_xor_sync(0xffffffffu, ss, o);
    float nrm = fmaxf(sqrtf(ss), 1e-12f);
    g[lane]      = sigmoidf_(v0 / nrm);
    g[lane + 32] = sigmoidf_(v1 / nrm);
}

// ================= bilinear =================
__global__ void bilinear_kernel(const float* __restrict__ EMB,
                                const float* __restrict__ G,
                                const float* __restrict__ Wb, const float* __restrict__ bb,
                                float* ret, float* reta)
{
    __shared__ float sW[64 * 65];
    __shared__ float sg[8][64];
    __shared__ float sga[8][64];
    for (int i = threadIdx.x; i < 64 * 64; i += blockDim.x)
        sW[(i >> 6) * 65 + (i & 63)] = Wb[i];
    int warp = threadIdx.x >> 5, lane = threadIdx.x & 31;
    int n = blockIdx.x * 8 + warp;
    sg[warp][lane]       = G[(size_t)n * 64 + lane];
    sg[warp][lane + 32]  = G[(size_t)n * 64 + lane + 32];
    sga[warp][lane]      = G[262144 + (size_t)n * 64 + lane];
    sga[warp][lane + 32] = G[262144 + (size_t)n * 64 + lane + 32];
    __syncthreads();

    float wcf0 = 0.f, wcf1 = 0.f, wca0 = 0.f, wca1 = 0.f;
    #pragma unroll 8
    for (int k2 = 0; k2 < 64; k2++) {
        float w0 = sW[lane * 65 + k2];
        float w1 = sW[(lane + 32) * 65 + k2];
        float gv = sg[warp][k2], gav = sga[warp][k2];
        wcf0 = fmaf(w0, gv, wcf0);  wcf1 = fmaf(w1, gv, wcf1);
        wca0 = fmaf(w0, gav, wca0); wca1 = fmaf(w1, gav, wca1);
    }
    float e0 = EMB[(size_t)n * 128 + lane],      e1 = EMB[(size_t)n * 128 + lane + 32];
    float a0 = EMB[(size_t)n * 128 + 64 + lane], a1 = EMB[(size_t)n * 128 + 64 + lane + 32];
    float d1 = e0 * wcf0 + e1 * wcf1;
    float d2 = a0 * wcf0 + a1 * wcf1;
    float d3 = a0 * wca0 + a1 * wca1;
    float d4 = e0 * wca0 + e1 * wca1;
    #pragma unroll
    for (int o = 16; o; o >>= 1) {
        d1 += __shfl_xor_sync(0xffffffffu, d1, o);
        d2 += __shfl_xor_sync(0xffffffffu, d2, o);
        d3 += __shfl_xor_sync(0xffffffffu, d3, o);
        d4 += __shfl_xor_sync(0xffffffffu, d4, o);
    }
    if (lane == 0) {
        float bias = bb[0];
        ret[n * 2 + 0]  = sigmoidf_(d1 + bias);
        ret[n * 2 + 1]  = sigmoidf_(d2 + bias);
        reta[n * 2 + 0] = sigmoidf_(d3 + bias);
        reta[n * 2 + 1] = sigmoidf_(d4 + bias);
    }
}

// ================= launch =================
extern "C" void kernel_launch(void* const* d_in, const int* in_sizes, int n_in,
                              void* d_out, int out_size)
{
    const float* feat  = (const float*)d_in[0];
    const float* feata = (const float*)d_in[1];
    const float* adj   = (const float*)d_in[2];
    const float* gn    = (const float*)d_in[3];
    const float* Wl1   = (const float*)d_in[4];
    const float* Wr1   = (const float*)d_in[5];
    const float* att1  = (const float*)d_in[6];
    const float* Wl2   = (const float*)d_in[7];
    const float* Wr2   = (const float*)d_in[8];
    const float* att2  = (const float*)d_in[9];
    const float* Wb    = (const float*)d_in[10];
    const float* bb    = (const float*)d_in[11];
    const int*   src   = (const int*)d_in[12];
    const int*   dst   = (const int*)d_in[13];
    float* out = (float*)d_out;

    float* sc = nullptr;
    __nv_bfloat16* bs = nullptr;
    cudaGetSymbolAddress((void**)&sc, g_fscratch);
    cudaGetSymbolAddress((void**)&bs, g_bscratch);

    dim3 tb(32, 8);

    // init
    zero_kernel<<<2048, 256>>>(sc, FSCRATCH_N);
    fill_kernel<<<32, 256>>>(sc + OFF_EMAX1, 8192, -INFINITY);
    fill_kernel<<<16, 256>>>(sc + OFF_EMAX2, 4096, -INFINITY);

    // hi/lo conversions of inputs
    rconv<<<32768, 256>>>(adj, bs + B_ADJ_HI, bs + B_ADJ_LO, 8388608);
    rconv<<<32768, 256>>>(gn,  bs + B_GN_HI,  bs + B_GN_LO,  8388608);
    rconv<<<4096, 256>>>(feat,  bs + B_FEAT_HI,           bs + B_FEAT_LO,           1048576);
    rconv<<<4096, 256>>>(feata, bs + B_FEAT_HI + 2097152, bs + B_FEAT_LO + 2097152, 1048576);
    tconv<<<dim3(2, 16), tb>>>(Wl1, 64, bs + B_W1T_HI, bs + B_W1T_LO, 512, 0);
    tconv<<<dim3(2, 16), tb>>>(Wr1, 64, bs + B_W1T_HI, bs + B_W1T_LO, 512, 64);
    tconv<<<dim3(16, 2), tb>>>(Wl2, 512, bs + B_W2T_HI, bs + B_W2T_LO, 64, 0);
    tconv<<<dim3(16, 2), tb>>>(Wr2, 512, bs + B_W2T_HI, bs + B_W2T_LO, 64, 512);

    // GEMM1: X1[b] = feat_b @ [Wl1|Wr1]  (M=4096,N=128,K=512; batch=2, split-K=2)
    mma_gemm<<<dim3(32, 1, 4), 256>>>(
        bs + B_FEAT_HI, bs + B_FEAT_LO, 512, bs + B_W1T_HI, bs + B_W1T_LO, 512,
        sc + OFF_X1, 128, 512, 2, 256, 2097152, 524288, 1);

    // GAT layer 1
    edge_e<64><<<dim3(NE / 8, 2), 256>>>(sc + OFF_X1, sc + OFF_X1 + 64, 128, att1, src, dst,
                                         sc + OFF_E1, sc + OFF_EMAX1, 524288, 65536, 4096);
    edge_sm<<<dim3(NE / 256, 2), 256>>>(sc + OFF_E1, sc + OFF_EMAX1, sc + OFF_DEN1, dst, 65536, 4096);
    edge_agg<64><<<dim3(NE / 8, 2), 256>>>(sc + OFF_E1, sc + OFF_DEN1, sc + OFF_X1, 128, src, dst,
                                           sc + OFF_AGG1, 524288, 65536, 4096, 262144);

    // transpose agg1 -> A1T [128][4096]
    tconv<<<dim3(2, 128), tb>>>(sc + OFF_AGG1,          64, bs + B_A1T_HI, bs + B_A1T_LO, 4096, 0);
    tconv<<<dim3(2, 128), tb>>>(sc + OFF_AGG1 + 262144, 64, bs + B_A1T_HI, bs + B_A1T_LO, 4096, 64);

    // GEMM2: Z = adj @ [agg1_f|agg1_a]  (M=4096,N=128,K=4096; split-K=4)
    mma_gemm<<<dim3(32, 1, 4), 256>>>(
        bs + B_ADJ_HI, bs + B_ADJ_LO, 4096, bs + B_A1T_HI, bs + B_A1T_LO, 4096,
        sc + OFF_Z, 128, 4096, 4, 1024, 0, 0, 1);

    // hiden_emb, emb/emb_a, z hi/lo for layer2
    copy_z_kernel<<<1024, 256>>>(sc + OFF_Z, out);
    relu_kernel<<<2048, 256>>>(sc + OFF_Z, sc + OFF_EMB, 524288);
    rconv<<<1024, 256>>>(sc + OFF_Z, bs + B_Z_HI, bs + B_Z_LO, 262144);

    // GEMM3: X2 = z @ [Wl2|Wr2]  (M=4096,N=1024,K=64)
    mma_gemm<<<dim3(32, 8, 1), 256>>>(
        bs + B_Z_HI, bs + B_Z_LO, 128, bs + B_W2T_HI, bs + B_W2T_LO, 64,
        sc + OFF_X2, 1024, 64, 1, 64, 0, 0, 0);

    // GAT layer 2
    edge_e<512><<<dim3(NE / 8, 1), 256>>>(sc + OFF_X2, sc + OFF_X2 + 512, 1024, att2, src, dst,
                                          sc + OFF_E2, sc + OFF_EMAX2, 0, 0, 0);
    edge_sm<<<dim3(NE / 256, 1), 256>>>(sc + OFF_E2, sc + OFF_EMAX2, sc + OFF_DEN2, dst, 0, 0);
    edge_agg<512><<<dim3(NE / 8, 1), 256>>>(sc + OFF_E2, sc + OFF_DEN2, sc + OFF_X2, 1024, src, dst,
                                            sc + OFF_AGG2, 0, 0, 0, 0);

    // transpose agg2 -> A2T [512][4096]
    tconv<<<dim3(16, 128), tb>>>(sc + OFF_AGG2, 512, bs + B_A2T_HI, bs + B_A2T_LO, 4096, 0);

    // GEMM4: h = adj @ agg2  (M=4096,N=512,K=4096) -> out directly
    mma_gemm<<<dim3(32, 4, 1), 256>>>(
        bs + B_ADJ_HI, bs + B_ADJ_LO, 4096, bs + B_A2T_HI, bs + B_A2T_LO, 4096,
        out + 262144, 512, 4096, 1, 4096, 0, 0, 0);

    // transpose emb -> EMBT [128][4096]
    tconv<<<dim3(2, 128), tb>>>(sc + OFF_EMB,      128, bs + B_EMBT_HI, bs + B_EMBT_LO, 4096, 0);
    tconv<<<dim3(2, 128), tb>>>(sc + OFF_EMB + 64, 128, bs + B_EMBT_HI, bs + B_EMBT_LO, 4096, 64);

    // GEMM5: VS = gn @ [emb|emb_a]  (M=4096,N=128,K=4096; split-K=4)
    mma_gemm<<<dim3(32, 1, 4), 256>>>(
        bs + B_GN_HI, bs + B_GN_LO, 4096, bs + B_EMBT_HI, bs + B_EMBT_LO, 4096,
        sc + OFF_VS, 128, 4096, 4, 1024, 0, 0, 1);

    // readout + bilinear
    rowsum_kernel<<<512, 256>>>(gn, sc + OFF_RS);
    readout_g<<<dim3(512, 2), 256>>>(sc + OFF_VS, sc + OFF_RS, sc + OFF_G);
    bilinear_kernel<<<512, 256>>>(sc + OFF_EMB, sc + OFF_G, Wb, bb,
                                  out + 2359296, out + 2367488);
}

// round 5
// speedup vs baseline: 2.7209x; 1.4409x over previous
#include <cuda_runtime.h>
#include <cuda_bf16.h>
#include <cstdint>
#include <math.h>

#define NN 4096
#define NE 65536

// ================= float scratch (element offsets) =================
#define OFF_X1    0u          /* [2][4096][128] xl|xr */
#define OFF_Z     1048576u    /* [4096][128] z|z_a */
#define OFF_EMB   1572864u    /* [4096][128] emb|emb_a */
#define OFF_X2    2097152u    /* [4096][1024] xl2|xr2 */
#define OFF_AGG1  6291456u    /* [2][4096][64] */
#define OFF_AGG2  6815744u    /* [4096][512] */
#define OFF_VS    8912896u    /* [4096][128] vs|vs_a */
#define OFF_E1    9437184u    /* [2][65536] */
#define OFF_E2    9584640u    /* [65536] */
#define OFF_G     9658368u    /* [2][4096][64] */
#define OFF_RS    10182656u
#define FSCRATCH_N 10186752u
__device__ __align__(16) float g_fscratch[FSCRATCH_N];

// ================= bf16 scratch (B operands, N x K hi/lo) =================
#define B_W1T_HI  0u          /* [128][512] */
#define B_W1T_LO  65536u
#define B_W2T_HI  131072u     /* [1024][64] */
#define B_W2T_LO  196608u
#define B_A1T_HI  262144u     /* [128][4096] */
#define B_A1T_LO  786432u
#define B_EMBT_HI 1310720u    /* [128][4096] */
#define B_EMBT_LO 1835008u
#define B_A2T_HI  2359296u    /* [512][4096] */
#define B_A2T_LO  4456448u
#define BSCRATCH_N 6553600u
__device__ __align__(16) __nv_bfloat16 g_bscratch[BSCRATCH_N];

// ================= int scratch (CSR) =================
#define I_HIST 0u        /* [256 blocks][4096] b-major */
#define I_CNT  1048576u  /* [4096] */
#define I_BASE 1052672u  /* [4097] */
#define I_SSRC 1056769u  /* [65536] src sorted by CSR position */
#define ISCRATCH_N 1122306u
__device__ int g_iscratch[ISCRATCH_N];

// ================= warp-MMA helpers =================
__device__ __forceinline__ uint32_t smem_u32(const void* p) {
    uint32_t a;
    asm("{ .reg .u64 t; cvta.to.shared.u64 t, %1; cvt.u32.u64 %0, t; }" : "=r"(a) : "l"(p));
    return a;
}
__device__ __forceinline__ void cp_async16(uint32_t saddr, const void* gaddr) {
    asm volatile("cp.async.cg.shared.global [%0], [%1], 16;" :: "r"(saddr), "l"(gaddr));
}
#define CP_COMMIT() asm volatile("cp.async.commit_group;" ::: "memory")
#define CP_WAIT(N)  asm volatile("cp.async.wait_group %0;" :: "n"(N) : "memory")

__device__ __forceinline__ void ldsm4(uint32_t* r, uint32_t addr) {
    asm volatile("ldmatrix.sync.aligned.m8n8.x4.shared.b16 {%0,%1,%2,%3}, [%4];"
        : "=r"(r[0]), "=r"(r[1]), "=r"(r[2]), "=r"(r[3]) : "r"(addr));
}
__device__ __forceinline__ void mma16816(float* d, const uint32_t* a, uint32_t b0, uint32_t b1) {
    asm volatile("mma.sync.aligned.m16n8k16.row.col.f32.bf16.bf16.f32 "
        "{%0,%1,%2,%3}, {%4,%5,%6,%7}, {%8,%9}, {%0,%1,%2,%3};"
        : "+f"(d[0]), "+f"(d[1]), "+f"(d[2]), "+f"(d[3])
        : "r"(a[0]), "r"(a[1]), "r"(a[2]), "r"(a[3]), "r"(b0), "r"(b1));
}

// ====== fused-precision GEMM: C[M,N]fp32 = A(fp32)[M,K] @ Bt(bf16 hi/lo)[N,K]^T =====
// acc += Ahi*Bhi + Ahi*Blo + Alo*Bhi per 32-k chunk, single K pass.
// 128x128 tile, 256 threads (8 warps 4Mx2N), smem stage = Ahi|Alo|Bhi|Blo (10240B each).
#define STG4 40960
__global__ __launch_bounds__(256) void mma_gemm_f32(
    const float* __restrict__ A, int lda,
    const __nv_bfloat16* __restrict__ Bthi, const __nv_bfloat16* __restrict__ Btlo, int ldb,
    float* __restrict__ C, int ldC, int K, int kPerSplit, int doAtomic)
{
    extern __shared__ __align__(16) char sm[];
    int tid = threadIdx.x, lane = tid & 31, wid = tid >> 5;
    int warpM = wid & 3, warpN = wid >> 2;
    int m0 = blockIdx.x * 128, n0 = blockIdx.y * 128;
    int split = blockIdx.z;
    int kBeg = split * kPerSplit;
    int kEnd = kBeg + kPerSplit; if (kEnd > K) kEnd = K;
    int nk = (kEnd - kBeg) >> 5;
    uint32_t smBase = smem_u32(sm);

    float acc[2][8][4];
    #pragma unroll
    for (int t = 0; t < 2; t++)
        #pragma unroll
        for (int n = 0; n < 8; n++)
            #pragma unroll
            for (int j = 0; j < 4; j++) acc[t][n][j] = 0.f;

    int r0i = tid >> 2, c0i = tid & 3;           // rows 0..63
    int r1i = r0i + 64;                          // rows 64..127
    int arow0 = tid >> 2, ach = (tid & 3) * 8;   // A tasks: (arow0, ach), (arow0+64, ach)

    float4 aReg[4];
    auto load_B = [&](int s, int it) {
        int kt = kBeg + (it << 5);
        uint32_t bh = smBase + s * STG4 + 20480u;
        uint32_t bl = bh + 10240u;
        cp_async16(bh + r0i * 80 + c0i * 16, Bthi + (size_t)(n0 + r0i) * ldb + kt + c0i * 8);
        cp_async16(bh + r1i * 80 + c0i * 16, Bthi + (size_t)(n0 + r1i) * ldb + kt + c0i * 8);
        cp_async16(bl + r0i * 80 + c0i * 16, Btlo + (size_t)(n0 + r0i) * ldb + kt + c0i * 8);
        cp_async16(bl + r1i * 80 + c0i * 16, Btlo + (size_t)(n0 + r1i) * ldb + kt + c0i * 8);
        CP_COMMIT();
    };
    auto load_A = [&](int it) {
        int kt = kBeg + (it << 5);
        const float* p0 = A + (size_t)(m0 + arow0) * lda + kt + ach;
        const float* p1 = A + (size_t)(m0 + arow0 + 64) * lda + kt + ach;
        aReg[0] = *(const float4*)p0;
        aReg[1] = *(const float4*)(p0 + 4);
        aReg[2] = *(const float4*)p1;
        aReg[3] = *(const float4*)(p1 + 4);
    };
    auto st_A = [&](int s) {
        uint32_t ah = smBase + s * STG4;
        uint32_t al = ah + 10240u;
        #pragma unroll
        for (int task = 0; task < 2; task++) {
            float f[8];
            f[0] = aReg[2*task].x; f[1] = aReg[2*task].y; f[2] = aReg[2*task].z; f[3] = aReg[2*task].w;
            f[4] = aReg[2*task+1].x; f[5] = aReg[2*task+1].y; f[6] = aReg[2*task+1].z; f[7] = aReg[2*task+1].w;
            uint32_t hw[4], lw[4];
            #pragma unroll
            for (int q = 0; q < 4; q++) {
                __nv_bfloat16 h0 = __float2bfloat16_rn(f[2*q]);
                __nv_bfloat16 h1 = __float2bfloat16_rn(f[2*q+1]);
                __nv_bfloat16 l0 = __float2bfloat16_rn(f[2*q]   - __bfloat162float(h0));
                __nv_bfloat16 l1 = __float2bfloat16_rn(f[2*q+1] - __bfloat162float(h1));
                __nv_bfloat162 hp = __halves2bfloat162(h0, h1);
                __nv_bfloat162 lp = __halves2bfloat162(l0, l1);
                hw[q] = *(uint32_t*)&hp;
                lw[q] = *(uint32_t*)&lp;
            }
            uint32_t off = (uint32_t)(arow0 + task * 64) * 80 + (uint32_t)(ach * 2);
            *(uint4*)(sm + (ah - smBase) + off) = make_uint4(hw[0], hw[1], hw[2], hw[3]);
            *(uint4*)(sm + (al - smBase) + off) = make_uint4(lw[0], lw[1], lw[2], lw[3]);
        }
    };

    load_B(0, 0);
    load_A(0);
    st_A(0);
    int lrow = (lane & 7) + ((lane >> 3) & 1) * 8;
    int lkHalf = (lane >> 4);

    for (int it = 0; it < nk; ++it) {
        if (it + 1 < nk) { load_B((it + 1) & 1, it + 1); load_A(it + 1); CP_WAIT(1); }
        else             { CP_WAIT(0); }
        __syncthreads();
        uint32_t sAhi = smBase + (it & 1) * STG4;
        uint32_t sAlo = sAhi + 10240u;
        uint32_t sBhi = sAhi + 20480u;
        uint32_t sBlo = sAhi + 30720u;
        #pragma unroll
        for (int ks = 0; ks < 2; ks++) {
            int chunk = ks * 2 + lkHalf;
            uint32_t aH[2][4], aL[2][4], bH[4][4], bL[4][4];
            #pragma unroll
            for (int t = 0; t < 2; t++)
                ldsm4(aH[t], sAhi + (uint32_t)(warpM * 32 + t * 16 + lrow) * 80 + chunk * 16);
            #pragma unroll
            for (int p = 0; p < 4; p++)
                ldsm4(bH[p], sBhi + (uint32_t)(warpN * 64 + p * 16 + lrow) * 80 + chunk * 16);
            #pragma unroll
            for (int t = 0; t < 2; t++)
                #pragma unroll
                for (int nt = 0; nt < 8; nt++)
                    mma16816(acc[t][nt], aH[t], bH[nt >> 1][nt & 1], bH[nt >> 1][2 + (nt & 1)]);
            #pragma unroll
            for (int p = 0; p < 4; p++)
                ldsm4(bL[p], sBlo + (uint32_t)(warpN * 64 + p * 16 + lrow) * 80 + chunk * 16);
            #pragma unroll
            for (int t = 0; t < 2; t++)
                #pragma unroll
                for (int nt = 0; nt < 8; nt++)
                    mma16816(acc[t][nt], aH[t], bL[nt >> 1][nt & 1], bL[nt >> 1][2 + (nt & 1)]);
            #pragma unroll
            for (int t = 0; t < 2; t++)
                ldsm4(aL[t], sAlo + (uint32_t)(warpM * 32 + t * 16 + lrow) * 80 + chunk * 16);
            #pragma unroll
            for (int t = 0; t < 2; t++)
                #pragma unroll
                for (int nt = 0; nt < 8; nt++)
                    mma16816(acc[t][nt], aL[t], bH[nt >> 1][nt & 1], bH[nt >> 1][2 + (nt & 1)]);
        }
        if (it + 1 < nk) st_A((it + 1) & 1);
        __syncthreads();
    }

    int g = lane >> 2, q = lane & 3;
    #pragma unroll
    for (int t = 0; t < 2; t++) {
        #pragma unroll
        for (int nt = 0; nt < 8; nt++) {
            int row = m0 + warpM * 32 + t * 16 + g;
            int col = n0 + warpN * 64 + nt * 8 + q * 2;
            float* p0 = C + (size_t)row * ldC + col;
            float* p1 = C + (size_t)(row + 8) * ldC + col;
            if (doAtomic) {
                atomicAdd(p0,     acc[t][nt][0]); atomicAdd(p0 + 1, acc[t][nt][1]);
                atomicAdd(p1,     acc[t][nt][2]); atomicAdd(p1 + 1, acc[t][nt][3]);
            } else {
                *(float2*)p0 = make_float2(acc[t][nt][0], acc[t][nt][1]);
                *(float2*)p1 = make_float2(acc[t][nt][2], acc[t][nt][3]);
            }
        }
    }
}

// ================= CSR build (deterministic stable counting sort) ==========
__global__ void hist_k(const int* __restrict__ dst, int* __restrict__ hist) {
    __shared__ int hcnt[4096];
    int tid = threadIdx.x;
    for (int i = tid; i < 4096; i += 256) hcnt[i] = 0;
    __syncthreads();
    int d = dst[blockIdx.x * 256 + tid];
    atomicAdd(&hcnt[d], 1);
    __syncthreads();
    for (int i = tid; i < 4096; i += 256) hist[blockIdx.x * 4096 + i] = hcnt[i];
}
__global__ void scan_block_k(int* __restrict__ hist, int* __restrict__ cnt) {
    int d = blockIdx.x * 256 + threadIdx.x;
    int run = 0;
    for (int b = 0; b < 256; b++) {
        int o = b * 4096 + d;
        int v = hist[o];
        hist[o] = run;
        run += v;
    }
    cnt[d] = run;
}
__global__ void scan_total_k(const int* __restrict__ cnt, int* __restrict__ base) {
    __shared__ int s[1024];
    int t = threadIdx.x;
    int v0 = cnt[t*4], v1 = cnt[t*4+1], v2 = cnt[t*4+2], v3 = cnt[t*4+3];
    int tot = v0 + v1 + v2 + v3;
    s[t] = tot;
    __syncthreads();
    for (int off = 1; off < 1024; off <<= 1) {
        int x = (t >= off) ? s[t - off] : 0;
        __syncthreads();
        s[t] += x;
        __syncthreads();
    }
    int e = (t > 0) ? s[t - 1] : 0;
    base[t*4]   = e;
    base[t*4+1] = e + v0;
    base[t*4+2] = e + v0 + v1;
    base[t*4+3] = e + v0 + v1 + v2;
    if (t == 1023) base[4096] = s[1023];
}
__global__ void scatter_k(const int* __restrict__ src, const int* __restrict__ dst,
                          const int* __restrict__ hist, const int* __restrict__ base,
                          int* __restrict__ ssrc) {
    __shared__ int s_dst[256];
    int tid = threadIdx.x;
    int i = blockIdx.x * 256 + tid;
    int d = dst[i];
    s_dst[tid] = d;
    __syncthreads();
    int rank = 0;
    for (int j = 0; j < tid; j++) rank += (s_dst[j] == d);
    ssrc[base[d] + hist[blockIdx.x * 4096 + d] + rank] = src[i];
}

// ================= fused GATv2 per-dst kernel (no atomics) =================
__device__ __forceinline__ float sigmoidf_(float x) { return 1.f / (1.f + __expf(-x)); }

template<int D>
__global__ void gat_fused(const float* __restrict__ X, int ldx, int xrOff,
                          const float* __restrict__ att,
                          const int* __restrict__ base, const int* __restrict__ ssrc,
                          float* __restrict__ esc, float* __restrict__ agg, int ldagg,
                          long xBS, long eBS, long aggBS)
{
    int d = blockIdx.x, b = blockIdx.y;
    const float* Xb = X + (size_t)b * xBS;
    float* escb = esc + (size_t)b * eBS;
    float* out = agg + (size_t)b * aggBS + (size_t)d * ldagg;
    int beg = base[d];
    int deg = base[d + 1] - beg;
    int tid = threadIdx.x, warp = tid >> 5, lane = tid & 31;

    constexpr int NC = (D + 127) / 128;
    __shared__ float s_xr[D];
    __shared__ float s_red[4];
    __shared__ float s_bcast[2];
    __shared__ float s_alpha[128];
    __shared__ int   s_src[128];

    if (deg == 0) {
        for (int c = tid; c < D; c += 128) out[c] = 0.f;
        return;
    }
    for (int c = tid; c < D; c += 128) s_xr[c] = Xb[(size_t)d * ldx + xrOff + c];
    __syncthreads();

    // pass1: e scores (one warp per edge, strided)
    float wmax = -INFINITY;
    for (int e = warp; e < deg; e += 4) {
        const float* xr2 = Xb + (size_t)ssrc[beg + e] * ldx;
        float sum = 0.f;
        #pragma unroll
        for (int i = 0; i < D / 32; i++) {
            int idx = lane + i * 32;
            float v = xr2[idx] + s_xr[idx];
            v = v > 0.f ? v : 0.2f * v;
            sum = fmaf(v, att[idx], sum);
        }
        #pragma unroll
        for (int o = 16; o; o >>= 1) sum += __shfl_xor_sync(0xffffffffu, sum, o);
        if (lane == 0) escb[beg + e] = sum;
        wmax = fmaxf(wmax, sum);
    }
    if (lane == 0) s_red[warp] = wmax;
    __syncthreads();
    if (tid == 0) {
        float m = fmaxf(fmaxf(s_red[0], s_red[1]), fmaxf(s_red[2], s_red[3]));
        s_bcast[0] = m;
    }
    __syncthreads();
    float emax = s_bcast[0];

    // pass2: exp + sum
    float part = 0.f;
    for (int e = tid; e < deg; e += 128) {
        float ex = __expf(escb[beg + e] - emax);
        escb[beg + e] = ex;
        part += ex;
    }
    #pragma unroll
    for (int o = 16; o; o >>= 1) part += __shfl_xor_sync(0xffffffffu, part, o);
    if (lane == 0) s_red[warp] = part;
    __syncthreads();
    if (tid == 0) {
        float den = s_red[0] + s_red[1] + s_red[2] + s_red[3];
        s_bcast[1] = (den == 0.f) ? 1.f : den;
    }
    __syncthreads();
    float invden = 1.f / s_bcast[1];

    // pass3: aggregation, 128-edge chunks
    float acc[NC];
    #pragma unroll
    for (int j = 0; j < NC; j++) acc[j] = 0.f;
    for (int ch = 0; ch < deg; ch += 128) {
        int n = min(128, deg - ch);
        __syncthreads();
        if (tid < n) {
            s_alpha[tid] = escb[beg + ch + tid] * invden;
            s_src[tid] = ssrc[beg + ch + tid];
        }
        __syncthreads();
        for (int i = 0; i < n; i++) {
            float al = s_alpha[i];
            const float* xr2 = Xb + (size_t)s_src[i] * ldx;
            #pragma unroll
            for (int j = 0; j < NC; j++) {
                int c = tid + j * 128;
                if (c < D) acc[j] = fmaf(al, xr2[c], acc[j]);
            }
        }
    }
    #pragma unroll
    for (int j = 0; j < NC; j++) {
        int c = tid + j * 128;
        if (c < D) out[c] = acc[j];
    }
}

// ================= conversions / utility =================
__global__ void tconv(const float* __restrict__ src, int ldSrc,
                      __nv_bfloat16* __restrict__ dhi, __nv_bfloat16* __restrict__ dlo,
                      int ldDst, int rowOff)
{
    __shared__ float t[32][33];
    int rb = blockIdx.y * 32, cb = blockIdx.x * 32;
    int tx = threadIdx.x, ty = threadIdx.y;
    #pragma unroll
    for (int i = 0; i < 4; i++)
        t[ty + 8 * i][tx] = src[(size_t)(rb + ty + 8 * i) * ldSrc + cb + tx];
    __syncthreads();
    #pragma unroll
    for (int i = 0; i < 4; i++) {
        int c = cb + ty + 8 * i;
        float v = t[tx][ty + 8 * i];
        __nv_bfloat16 h = __float2bfloat16_rn(v);
        size_t o = (size_t)(c + rowOff) * ldDst + rb + tx;
        dhi[o] = h;
        dlo[o] = __float2bfloat16_rn(v - __bfloat162float(h));
    }
}
__global__ void zero_kernel(float* p, int n) {
    int i = blockIdx.x * blockDim.x + threadIdx.x;
    int stride = gridDim.x * blockDim.x;
    float4* p4 = (float4*)p;
    int n4 = n >> 2;
    for (int j = i; j < n4; j += stride) p4[j] = make_float4(0.f, 0.f, 0.f, 0.f);
}
__global__ void relu_kernel(const float* __restrict__ z, float* __restrict__ emb, int n) {
    int i = blockIdx.x * blockDim.x + threadIdx.x;
    if (i < n) emb[i] = fmaxf(z[i], 0.f);
}
__global__ void copy_z_kernel(const float* __restrict__ Z, float* __restrict__ out) {
    int i = blockIdx.x * blockDim.x + threadIdx.x;
    int n = i >> 6, c = i & 63;
    out[i] = Z[n * 128 + c];
}

// ================= readout =================
__global__ void rowsum_kernel(const float* __restrict__ gnm, float* rs)
{
    int warp = threadIdx.x >> 5, lane = threadIdx.x & 31;
    int row = blockIdx.x * 8 + warp;
    const float4* p = (const float4*)(gnm + (size_t)row * NN);
    float s = 0.f;
    for (int i = lane; i < NN / 4; i += 32) { float4 v = p[i]; s += (v.x + v.y) + (v.z + v.w); }
    #pragma unroll
    for (int o = 16; o; o >>= 1) s += __shfl_xor_sync(0xffffffffu, s, o);
    if (lane == 0) rs[row] = s;
}
__global__ void readout_g(const float* __restrict__ VS, const float* __restrict__ rs,
                          float* __restrict__ G)
{
    int b = blockIdx.y;
    int warp = threadIdx.x >> 5, lane = threadIdx.x & 31;
    int n = blockIdx.x * 8 + warp;
    const float* vs = VS + (size_t)n * 128 + b * 64;
    float* g = G + (size_t)b * 262144 + (size_t)n * 64;
    float inv = 1.f / rs[n];
    float v0 = vs[lane] * inv;
    float v1 = vs[lane + 32] * inv;
    float ss = v0 * v0 + v1 * v1;
    #pragma unroll
    for (int o = 16; o; o >>= 1) ss += __shfl_xor_sync(0xffffffffu, ss, o);
    float nrm = fmaxf(sqrtf(ss), 1e-12f);
    g[lane]      = sigmoidf_(v0 / nrm);
    g[lane + 32] = sigmoidf_(v1 / nrm);
}

// ================= bilinear =================
__global__ void bilinear_kernel(const float* __restrict__ EMB,
                                const float* __restrict__ G,
                                const float* __restrict__ Wb, const float* __restrict__ bb,
                                float* ret, float* reta)
{
    __shared__ float sW[64 * 65];
    __shared__ float sg[8][64];
    __shared__ float sga[8][64];
    for (int i = threadIdx.x; i < 64 * 64; i += blockDim.x)
        sW[(i >> 6) * 65 + (i & 63)] = Wb[i];
    int warp = threadIdx.x >> 5, lane = threadIdx.x & 31;
    int n = blockIdx.x * 8 + warp;
    sg[warp][lane]       = G[(size_t)n * 64 + lane];
    sg[warp][lane + 32]  = G[(size_t)n * 64 + lane + 32];
    sga[warp][lane]      = G[262144 + (size_t)n * 64 + lane];
    sga[warp][lane + 32] = G[262144 + (size_t)n * 64 + lane + 32];
    __syncthreads();
    float wcf0 = 0.f, wcf1 = 0.f, wca0 = 0.f, wca1 = 0.f;
    #pragma unroll 8
    for (int k2 = 0; k2 < 64; k2++) {
        float w0 = sW[lane * 65 + k2];
        float w1 = sW[(lane + 32) * 65 + k2];
        float gv = sg[warp][k2], gav = sga[warp][k2];
        wcf0 = fmaf(w0, gv, wcf0);  wcf1 = fmaf(w1, gv, wcf1);
        wca0 = fmaf(w0, gav, wca0); wca1 = fmaf(w1, gav, wca1);
    }
    float e0 = EMB[(size_t)n * 128 + lane],      e1 = EMB[(size_t)n * 128 + lane + 32];
    float a0 = EMB[(size_t)n * 128 + 64 + lane], a1 = EMB[(size_t)n * 128 + 64 + lane + 32];
    float d1 = e0 * wcf0 + e1 * wcf1;
    float d2 = a0 * wcf0 + a1 * wcf1;
    float d3 = a0 * wca0 + a1 * wca1;
    float d4 = e0 * wca0 + e1 * wca1;
    #pragma unroll
    for (int o = 16; o; o >>= 1) {
        d1 += __shfl_xor_sync(0xffffffffu, d1, o);
        d2 += __shfl_xor_sync(0xffffffffu, d2, o);
        d3 += __shfl_xor_sync(0xffffffffu, d3, o);
        d4 += __shfl_xor_sync(0xffffffffu, d4, o);
    }
    if (lane == 0) {
        float bias = bb[0];
        ret[n * 2 + 0]  = sigmoidf_(d1 + bias);
        ret[n * 2 + 1]  = sigmoidf_(d2 + bias);
        reta[n * 2 + 0] = sigmoidf_(d3 + bias);
        reta[n * 2 + 1] = sigmoidf_(d4 + bias);
    }
}

// ================= launch =================
extern "C" void kernel_launch(void* const* d_in, const int* in_sizes, int n_in,
                              void* d_out, int out_size)
{
    const float* feat  = (const float*)d_in[0];
    const float* feata = (const float*)d_in[1];
    const float* adj   = (const float*)d_in[2];
    const float* gn    = (const float*)d_in[3];
    const float* Wl1   = (const float*)d_in[4];
    const float* Wr1   = (const float*)d_in[5];
    const float* att1  = (const float*)d_in[6];
    const float* Wl2   = (const float*)d_in[7];
    const float* Wr2   = (const float*)d_in[8];
    const float* att2  = (const float*)d_in[9];
    const float* Wb    = (const float*)d_in[10];
    const float* bb    = (const float*)d_in[11];
    const int*   src   = (const int*)d_in[12];
    const int*   dst   = (const int*)d_in[13];
    float* out = (float*)d_out;

    float* sc = nullptr;
    __nv_bfloat16* bs = nullptr;
    int* is = nullptr;
    cudaGetSymbolAddress((void**)&sc, g_fscratch);
    cudaGetSymbolAddress((void**)&bs, g_bscratch);
    cudaGetSymbolAddress((void**)&is, g_iscratch);
    cudaFuncSetAttribute(mma_gemm_f32, cudaFuncAttributeMaxDynamicSharedMemorySize, 2 * STG4);

    dim3 tb(32, 8);

    // zero split-K accumulators (X1+Z contiguous, VS separate)
    zero_kernel<<<512, 256>>>(sc, 1572864);
    zero_kernel<<<256, 256>>>(sc + OFF_VS, 524288);

    // CSR build (deterministic)
    hist_k<<<256, 256>>>(dst, is + I_HIST);
    scan_block_k<<<16, 256>>>(is + I_HIST, is + I_CNT);
    scan_total_k<<<1, 1024>>>(is + I_CNT, is + I_BASE);
    scatter_k<<<256, 256>>>(src, dst, is + I_HIST, is + I_BASE, is + I_SSRC);

    // weight transposes
    tconv<<<dim3(2, 16), tb>>>(Wl1, 64, bs + B_W1T_HI, bs + B_W1T_LO, 512, 0);
    tconv<<<dim3(2, 16), tb>>>(Wr1, 64, bs + B_W1T_HI, bs + B_W1T_LO, 512, 64);
    tconv<<<dim3(16, 2), tb>>>(Wl2, 512, bs + B_W2T_HI, bs + B_W2T_LO, 64, 0);
    tconv<<<dim3(16, 2), tb>>>(Wr2, 512, bs + B_W2T_HI, bs + B_W2T_LO, 64, 512);

    // GEMM1: X1[b] = feat_b @ [Wl1|Wr1]  (M=4096,N=128,K=512; split-K=4 atomic)
    mma_gemm_f32<<<dim3(32, 1, 4), 256, 2 * STG4>>>(
        feat, 512, bs + B_W1T_HI, bs + B_W1T_LO, 512, sc + OFF_X1, 128, 512, 128, 1);
    mma_gemm_f32<<<dim3(32, 1, 4), 256, 2 * STG4>>>(
        feata, 512, bs + B_W1T_HI, bs + B_W1T_LO, 512, sc + OFF_X1 + 524288, 128, 512, 128, 1);

    // GAT layer 1 (fused, batch 2)
    gat_fused<64><<<dim3(4096, 2), 128>>>(sc + OFF_X1, 128, 64, att1,
        is + I_BASE, is + I_SSRC, sc + OFF_E1, sc + OFF_AGG1, 64, 524288, 65536, 262144);

    // transpose agg1 -> A1T [128][4096]
    tconv<<<dim3(2, 128), tb>>>(sc + OFF_AGG1,          64, bs + B_A1T_HI, bs + B_A1T_LO, 4096, 0);
    tconv<<<dim3(2, 128), tb>>>(sc + OFF_AGG1 + 262144, 64, bs + B_A1T_HI, bs + B_A1T_LO, 4096, 64);

    // GEMM2: Z = adj @ [agg1_f|agg1_a]  (M=4096,N=128,K=4096; split-K=4 atomic)
    mma_gemm_f32<<<dim3(32, 1, 4), 256, 2 * STG4>>>(
        adj, 4096, bs + B_A1T_HI, bs + B_A1T_LO, 4096, sc + OFF_Z, 128, 4096, 1024, 1);

    copy_z_kernel<<<1024, 256>>>(sc + OFF_Z, out);
    relu_kernel<<<2048, 256>>>(sc + OFF_Z, sc + OFF_EMB, 524288);

    // GEMM3: X2 = z @ [Wl2|Wr2]  (M=4096,N=1024,K=64; A = z fp32 ld=128)
    mma_gemm_f32<<<dim3(32, 8, 1), 256, 2 * STG4>>>(
        sc + OFF_Z, 128, bs + B_W2T_HI, bs + B_W2T_LO, 64, sc + OFF_X2, 1024, 64, 64, 0);

    // GAT layer 2 (fused)
    gat_fused<512><<<dim3(4096, 1), 128>>>(sc + OFF_X2, 1024, 512, att2,
        is + I_BASE, is + I_SSRC, sc + OFF_E2, sc + OFF_AGG2, 512, 0, 0, 0);

    // transpose agg2 -> A2T [512][4096]
    tconv<<<dim3(16, 128), tb>>>(sc + OFF_AGG2, 512, bs + B_A2T_HI, bs + B_A2T_LO, 4096, 0);

    // GEMM4: h = adj @ agg2  (M=4096,N=512,K=4096) -> out directly
    mma_gemm_f32<<<dim3(32, 4, 1), 256, 2 * STG4>>>(
        adj, 4096, bs + B_A2T_HI, bs + B_A2T_LO, 4096, out + 262144, 512, 4096, 4096, 0);

    // transpose emb -> EMBT [128][4096]
    tconv<<<dim3(2, 128), tb>>>(sc + OFF_EMB,      128, bs + B_EMBT_HI, bs + B_EMBT_LO, 4096, 0);
    tconv<<<dim3(2, 128), tb>>>(sc + OFF_EMB + 64, 128, bs + B_EMBT_HI, bs + B_EMBT_LO, 4096, 64);

    // GEMM5: VS = gn @ [emb|emb_a]  (M=4096,N=128,K=4096; split-K=4 atomic)
    mma_gemm_f32<<<dim3(32, 1, 4), 256, 2 * STG4>>>(
        gn, 4096, bs + B_EMBT_HI, bs + B_EMBT_LO, 4096, sc + OFF_VS, 128, 4096, 1024, 1);

    // readout + bilinear
    rowsum_kernel<<<512, 256>>>(gn, sc + OFF_RS);
    readout_g<<<dim3(512, 2), 256>>>(sc + OFF_VS, sc + OFF_RS, sc + OFF_G);
    bilinear_kernel<<<512, 256>>>(sc + OFF_EMB, sc + OFF_G, Wb, bb,
                                  out + 2359296, out + 2367488);
}

// round 7
// speedup vs baseline: 2.7573x; 1.0134x over previous
#include <cuda_runtime.h>
#include <cuda_bf16.h>
#include <cstdint>
#include <math.h>

#define NN 4096
#define NE 65536

// ================= float scratch (element offsets) =================
#define OFF_X1    0u          /* [2][4096][128] xl|xr */
#define OFF_Z     1048576u    /* [4096][128] z|z_a */
#define OFF_EMB   1572864u    /* [4096][128] emb|emb_a */
#define OFF_X2    2097152u    /* [4096][1024] xl2|xr2 */
#define OFF_AGG1  6291456u    /* [2][4096][64] */
#define OFF_AGG2  6815744u    /* [4096][512] */
#define OFF_VS    8912896u    /* [4096][128] vs|vs_a */
#define OFF_E1    9437184u    /* [2][65536] */
#define OFF_E2    9584640u    /* [65536] */
#define OFF_G     9658368u    /* [2][4096][64] */
#define OFF_RS    10182656u
#define FSCRATCH_N 10186752u
__device__ __align__(16) float g_fscratch[FSCRATCH_N];

// ================= bf16 scratch (B operands, N x K hi/lo) =================
#define B_W1T_HI  0u          /* [128][512] */
#define B_W1T_LO  65536u
#define B_W2T_HI  131072u     /* [1024][64] */
#define B_W2T_LO  196608u
#define B_A1T_HI  262144u     /* [128][4096] */
#define B_A1T_LO  786432u
#define B_EMBT_HI 1310720u    /* [128][4096] */
#define B_EMBT_LO 1835008u
#define B_A2T_HI  2359296u    /* [512][4096] */
#define B_A2T_LO  4456448u
#define BSCRATCH_N 6553600u
__device__ __align__(16) __nv_bfloat16 g_bscratch[BSCRATCH_N];

// ================= int scratch (CSR) =================
#define I_HIST  0u         /* [256 blocks][4096] b-major */
#define I_HISTT 1048576u   /* [4096][256] d-major exclusive prefix */
#define I_CNT   2097152u   /* [4096] */
#define I_BASE  2101248u   /* [4097] */
#define I_SSRC  2105345u   /* [65536] */
#define ISCRATCH_N 2170882u
__device__ int g_iscratch[ISCRATCH_N];

// ================= warp-MMA helpers =================
__device__ __forceinline__ uint32_t smem_u32(const void* p) {
    uint32_t a;
    asm("{ .reg .u64 t; cvta.to.shared.u64 t, %1; cvt.u32.u64 %0, t; }" : "=r"(a) : "l"(p));
    return a;
}
__device__ __forceinline__ void cp_async16(uint32_t saddr, const void* gaddr) {
    asm volatile("cp.async.cg.shared.global [%0], [%1], 16;" :: "r"(saddr), "l"(gaddr));
}
#define CP_COMMIT() asm volatile("cp.async.commit_group;" ::: "memory")
#define CP_WAIT(N)  asm volatile("cp.async.wait_group %0;" :: "n"(N) : "memory")

__device__ __forceinline__ void ldsm4(uint32_t* r, uint32_t addr) {
    asm volatile("ldmatrix.sync.aligned.m8n8.x4.shared.b16 {%0,%1,%2,%3}, [%4];"
        : "=r"(r[0]), "=r"(r[1]), "=r"(r[2]), "=r"(r[3]) : "r"(addr));
}
__device__ __forceinline__ void mma16816(float* d, const uint32_t* a, uint32_t b0, uint32_t b1) {
    asm volatile("mma.sync.aligned.m16n8k16.row.col.f32.bf16.bf16.f32 "
        "{%0,%1,%2,%3}, {%4,%5,%6,%7}, {%8,%9}, {%0,%1,%2,%3};"
        : "+f"(d[0]), "+f"(d[1]), "+f"(d[2]), "+f"(d[3])
        : "r"(a[0]), "r"(a[1]), "r"(a[2]), "r"(a[3]), "r"(b0), "r"(b1));
}

// ====== fused-precision GEMM: C[M,N]fp32 = A(fp32)[M,K] @ Bt(bf16 hi/lo)[N,K]^T =====
// acc += Ahi*Bhi + Ahi*Blo (+ Alo*Bhi unless aExact) per 32-k chunk, single K pass.
#define STG4 40960
__global__ __launch_bounds__(256) void mma_gemm_f32(
    const float* __restrict__ A, int lda,
    const __nv_bfloat16* __restrict__ Bthi, const __nv_bfloat16* __restrict__ Btlo, int ldb,
    float* __restrict__ C, int ldC, int K, int kPerSplit, int doAtomic, int aExact)
{
    extern __shared__ __align__(16) char sm[];
    int tid = threadIdx.x, lane = tid & 31, wid = tid >> 5;
    int warpM = wid & 3, warpN = wid >> 2;
    int m0 = blockIdx.x * 128, n0 = blockIdx.y * 128;
    int split = blockIdx.z;
    int kBeg = split * kPerSplit;
    int kEnd = kBeg + kPerSplit; if (kEnd > K) kEnd = K;
    int nk = (kEnd - kBeg) >> 5;
    uint32_t smBase = smem_u32(sm);

    float acc[2][8][4];
    #pragma unroll
    for (int t = 0; t < 2; t++)
        #pragma unroll
        for (int n = 0; n < 8; n++)
            #pragma unroll
            for (int j = 0; j < 4; j++) acc[t][n][j] = 0.f;

    int r0i = tid >> 2, c0i = tid & 3;
    int r1i = r0i + 64;
    int arow0 = tid >> 2, ach = (tid & 3) * 8;

    float4 aReg[4];
    auto load_B = [&](int s, int it) {
        int kt = kBeg + (it << 5);
        uint32_t bh = smBase + s * STG4 + 20480u;
        uint32_t bl = bh + 10240u;
        cp_async16(bh + r0i * 80 + c0i * 16, Bthi + (size_t)(n0 + r0i) * ldb + kt + c0i * 8);
        cp_async16(bh + r1i * 80 + c0i * 16, Bthi + (size_t)(n0 + r1i) * ldb + kt + c0i * 8);
        cp_async16(bl + r0i * 80 + c0i * 16, Btlo + (size_t)(n0 + r0i) * ldb + kt + c0i * 8);
        cp_async16(bl + r1i * 80 + c0i * 16, Btlo + (size_t)(n0 + r1i) * ldb + kt + c0i * 8);
        CP_COMMIT();
    };
    auto load_A = [&](int it) {
        int kt = kBeg + (it << 5);
        const float* p0 = A + (size_t)(m0 + arow0) * lda + kt + ach;
        const float* p1 = A + (size_t)(m0 + arow0 + 64) * lda + kt + ach;
        aReg[0] = *(const float4*)p0;
        aReg[1] = *(const float4*)(p0 + 4);
        aReg[2] = *(const float4*)p1;
        aReg[3] = *(const float4*)(p1 + 4);
    };
    auto st_A = [&](int s) {
        uint32_t ah = smBase + s * STG4;
        uint32_t al = ah + 10240u;
        #pragma unroll
        for (int task = 0; task < 2; task++) {
            float f[8];
            f[0] = aReg[2*task].x; f[1] = aReg[2*task].y; f[2] = aReg[2*task].z; f[3] = aReg[2*task].w;
            f[4] = aReg[2*task+1].x; f[5] = aReg[2*task+1].y; f[6] = aReg[2*task+1].z; f[7] = aReg[2*task+1].w;
            uint32_t hw[4], lw[4];
            #pragma unroll
            for (int q = 0; q < 4; q++) {
                __nv_bfloat16 h0 = __float2bfloat16_rn(f[2*q]);
                __nv_bfloat16 h1 = __float2bfloat16_rn(f[2*q+1]);
                __nv_bfloat16 l0 = __float2bfloat16_rn(f[2*q]   - __bfloat162float(h0));
                __nv_bfloat16 l1 = __float2bfloat16_rn(f[2*q+1] - __bfloat162float(h1));
                __nv_bfloat162 hp = __halves2bfloat162(h0, h1);
                __nv_bfloat162 lp = __halves2bfloat162(l0, l1);
                hw[q] = *(uint32_t*)&hp;
                lw[q] = *(uint32_t*)&lp;
            }
            uint32_t off = (uint32_t)(arow0 + task * 64) * 80 + (uint32_t)(ach * 2);
            *(uint4*)(sm + (ah - smBase) + off) = make_uint4(hw[0], hw[1], hw[2], hw[3]);
            *(uint4*)(sm + (al - smBase) + off) = make_uint4(lw[0], lw[1], lw[2], lw[3]);
        }
    };

    load_B(0, 0);
    load_A(0);
    st_A(0);
    int lrow = (lane & 7) + ((lane >> 3) & 1) * 8;
    int lkHalf = (lane >> 4);

    for (int it = 0; it < nk; ++it) {
        if (it + 1 < nk) { load_B((it + 1) & 1, it + 1); load_A(it + 1); CP_WAIT(1); }
        else             { CP_WAIT(0); }
        __syncthreads();
        uint32_t sAhi = smBase + (it & 1) * STG4;
        uint32_t sAlo = sAhi + 10240u;
        uint32_t sBhi = sAhi + 20480u;
        uint32_t sBlo = sAhi + 30720u;
        #pragma unroll
        for (int ks = 0; ks < 2; ks++) {
            int chunk = ks * 2 + lkHalf;
            uint32_t aH[2][4], aL[2][4], bH[4][4], bL[4][4];
            #pragma unroll
            for (int t = 0; t < 2; t++)
                ldsm4(aH[t], sAhi + (uint32_t)(warpM * 32 + t * 16 + lrow) * 80 + chunk * 16);
            #pragma unroll
            for (int p = 0; p < 4; p++)
                ldsm4(bH[p], sBhi + (uint32_t)(warpN * 64 + p * 16 + lrow) * 80 + chunk * 16);
            #pragma unroll
            for (int t = 0; t < 2; t++)
                #pragma unroll
                for (int nt = 0; nt < 8; nt++)
                    mma16816(acc[t][nt], aH[t], bH[nt >> 1][nt & 1], bH[nt >> 1][2 + (nt & 1)]);
            #pragma unroll
            for (int p = 0; p < 4; p++)
                ldsm4(bL[p], sBlo + (uint32_t)(warpN * 64 + p * 16 + lrow) * 80 + chunk * 16);
            #pragma unroll
            for (int t = 0; t < 2; t++)
                #pragma unroll
                for (int nt = 0; nt < 8; nt++)
                    mma16816(acc[t][nt], aH[t], bL[nt >> 1][nt & 1], bL[nt >> 1][2 + (nt & 1)]);
            if (!aExact) {
                #pragma unroll
                for (int t = 0; t < 2; t++)
                    ldsm4(aL[t], sAlo + (uint32_t)(warpM * 32 + t * 16 + lrow) * 80 + chunk * 16);
                #pragma unroll
                for (int t = 0; t < 2; t++)
                    #pragma unroll
                    for (int nt = 0; nt < 8; nt++)
                        mma16816(acc[t][nt], aL[t], bH[nt >> 1][nt & 1], bH[nt >> 1][2 + (nt & 1)]);
            }
        }
        if (it + 1 < nk) st_A((it + 1) & 1);
        __syncthreads();
    }

    int g = lane >> 2, q = lane & 3;
    #pragma unroll
    for (int t = 0; t < 2; t++) {
        #pragma unroll
        for (int nt = 0; nt < 8; nt++) {
            int row = m0 + warpM * 32 + t * 16 + g;
            int col = n0 + warpN * 64 + nt * 8 + q * 2;
            float* p0 = C + (size_t)row * ldC + col;
            float* p1 = C + (size_t)(row + 8) * ldC + col;
            if (doAtomic) {
                atomicAdd(p0,     acc[t][nt][0]); atomicAdd(p0 + 1, acc[t][nt][1]);
                atomicAdd(p1,     acc[t][nt][2]); atomicAdd(p1 + 1, acc[t][nt][3]);
            } else {
                *(float2*)p0 = make_float2(acc[t][nt][0], acc[t][nt][1]);
                *(float2*)p1 = make_float2(acc[t][nt][2], acc[t][nt][3]);
            }
        }
    }
}

// ================= CSR build (deterministic stable counting sort) ==========
__global__ void hist_k(const int* __restrict__ dst, int* __restrict__ hist) {
    __shared__ int hcnt[4096];
    int tid = threadIdx.x;
    for (int i = tid; i < 4096; i += 256) hcnt[i] = 0;
    __syncthreads();
    int d = dst[blockIdx.x * 256 + tid];
    atomicAdd(&hcnt[d], 1);
    __syncthreads();
    for (int i = tid; i < 4096; i += 256) hist[blockIdx.x * 4096 + i] = hcnt[i];
}

// tiled transpose-scan: hist [256 b][4096 d] -> histT [4096 d][256 b] exclusive prefix over b
__global__ void scan_tile_k(const int* __restrict__ hist, int* __restrict__ histT,
                            int* __restrict__ cnt)
{
    __shared__ int s[256][33];
    int tid = threadIdx.x, lane = tid & 31, warp = tid >> 5;
    int d0 = blockIdx.x * 32;
    for (int bb = 0; bb < 256; bb += 8) {
        int b = bb + warp;
        s[b][lane] = hist[b * 4096 + d0 + lane];
    }
    __syncthreads();
    #pragma unroll
    for (int c = 0; c < 4; c++) {
        int dd = warp * 4 + c;
        int v[8], sum = 0;
        #pragma unroll
        for (int j = 0; j < 8; j++) { v[j] = s[lane * 8 + j][dd]; sum += v[j]; }
        int x = sum;
        #pragma unroll
        for (int o = 1; o < 32; o <<= 1) {
            int y = __shfl_up_sync(0xffffffffu, x, o);
            if (lane >= o) x += y;
        }
        int run = x - sum;  // exclusive
        #pragma unroll
        for (int j = 0; j < 8; j++) { s[lane * 8 + j][dd] = run; run += v[j]; }
        if (lane == 31) cnt[d0 + dd] = run;
    }
    __syncthreads();
    for (int t = tid; t < 32 * 256; t += 256) {
        int dd = t >> 8, b = t & 255;
        histT[(size_t)(d0 + dd) * 256 + b] = s[b][dd];
    }
}

__global__ void scan_total_k(const int* __restrict__ cnt, int* __restrict__ base) {
    __shared__ int wsum[32];
    int t = threadIdx.x, lane = t & 31, w = t >> 5;
    int v0 = cnt[t*4], v1 = cnt[t*4+1], v2 = cnt[t*4+2], v3 = cnt[t*4+3];
    int tot = v0 + v1 + v2 + v3;
    int x = tot;
    #pragma unroll
    for (int o = 1; o < 32; o <<= 1) {
        int y = __shfl_up_sync(0xffffffffu, x, o);
        if (lane >= o) x += y;
    }
    if (lane == 31) wsum[w] = x;
    __syncthreads();
    if (w == 0) {
        int s = wsum[lane];
        #pragma unroll
        for (int o = 1; o < 32; o <<= 1) {
            int y = __shfl_up_sync(0xffffffffu, s, o);
            if (lane >= o) s += y;
        }
        wsum[lane] = s;
    }
    __syncthreads();
    int woff = (w > 0) ? wsum[w - 1] : 0;
    int incl = x + woff;
    int e = incl - tot;
    base[t*4]   = e;
    base[t*4+1] = e + v0;
    base[t*4+2] = e + v0 + v1;
    base[t*4+3] = e + v0 + v1 + v2;
    if (t == 1023) base[4096] = incl;
}

__global__ void scatter_k(const int* __restrict__ src, const int* __restrict__ dst,
                          const int* __restrict__ histT, const int* __restrict__ base,
                          int* __restrict__ ssrc) {
    __shared__ int s_dst[256];
    int tid = threadIdx.x;
    int i = blockIdx.x * 256 + tid;
    int d = dst[i];
    s_dst[tid] = d;
    __syncthreads();
    int rank = 0;
    for (int j = 0; j < tid; j++) rank += (s_dst[j] == d);
    ssrc[base[d] + histT[(size_t)d * 256 + blockIdx.x] + rank] = src[i];
}

// ================= fused GATv2 per-dst kernel (no atomics) =================
__device__ __forceinline__ float sigmoidf_(float x) { return 1.f / (1.f + __expf(-x)); }

template<int D>
__global__ void gat_fused(const float* __restrict__ X, int ldx, int xrOff,
                          const float* __restrict__ att,
                          const int* __restrict__ base, const int* __restrict__ ssrc,
                          float* __restrict__ esc, float* __restrict__ agg, int ldagg,
                          long xBS, long eBS, long aggBS)
{
    int d = blockIdx.x, b = blockIdx.y;
    const float* Xb = X + (size_t)b * xBS;
    float* escb = esc + (size_t)b * eBS;
    float* out = agg + (size_t)b * aggBS + (size_t)d * ldagg;
    int beg = base[d];
    int deg = base[d + 1] - beg;
    int tid = threadIdx.x, warp = tid >> 5, lane = tid & 31;

    constexpr int NC = (D + 127) / 128;
    __shared__ float s_xr[D];
    __shared__ float s_red[4];
    __shared__ float s_bcast[2];
    __shared__ float s_alpha[128];
    __shared__ int   s_src[128];

    if (deg == 0) {
        for (int c = tid; c < D; c += 128) out[c] = 0.f;
        return;
    }
    for (int c = tid; c < D; c += 128) s_xr[c] = Xb[(size_t)d * ldx + xrOff + c];
    __syncthreads();

    float wmax = -INFINITY;
    for (int e = warp; e < deg; e += 4) {
        const float* xr2 = Xb + (size_t)ssrc[beg + e] * ldx;
        float sum = 0.f;
        #pragma unroll
        for (int i = 0; i < D / 32; i++) {
            int idx = lane + i * 32;
            float v = xr2[idx] + s_xr[idx];
            v = v > 0.f ? v : 0.2f * v;
            sum = fmaf(v, att[idx], sum);
        }
        #pragma unroll
        for (int o = 16; o; o >>= 1) sum += __shfl_xor_sync(0xffffffffu, sum, o);
        if (lane == 0) escb[beg + e] = sum;
        wmax = fmaxf(wmax, sum);
    }
    if (lane == 0) s_red[warp] = wmax;
    __syncthreads();
    if (tid == 0) {
        float m = fmaxf(fmaxf(s_red[0], s_red[1]), fmaxf(s_red[2], s_red[3]));
        s_bcast[0] = m;
    }
    __syncthreads();
    float emax = s_bcast[0];

    float part = 0.f;
    for (int e = tid; e < deg; e += 128) {
        float ex = __expf(escb[beg + e] - emax);
        escb[beg + e] = ex;
        part += ex;
    }
    #pragma unroll
    for (int o = 16; o; o >>= 1) part += __shfl_xor_sync(0xffffffffu, part, o);
    if (lane == 0) s_red[warp] = part;
    __syncthreads();
    if (tid == 0) {
        float den = s_red[0] + s_red[1] + s_red[2] + s_red[3];
        s_bcast[1] = (den == 0.f) ? 1.f : den;
    }
    __syncthreads();
    float invden = 1.f / s_bcast[1];

    float acc[NC];
    #pragma unroll
    for (int j = 0; j < NC; j++) acc[j] = 0.f;
    for (int ch = 0; ch < deg; ch += 128) {
        int n = min(128, deg - ch);
        __syncthreads();
        if (tid < n) {
            s_alpha[tid] = escb[beg + ch + tid] * invden;
            s_src[tid] = ssrc[beg + ch + tid];
        }
        __syncthreads();
        for (int i = 0; i < n; i++) {
            float al = s_alpha[i];
            const float* xr2 = Xb + (size_t)s_src[i] * ldx;
            #pragma unroll
            for (int j = 0; j < NC; j++) {
                int c = tid + j * 128;
                if (c < D) acc[j] = fmaf(al, xr2[c], acc[j]);
            }
        }
    }
    #pragma unroll
    for (int j = 0; j < NC; j++) {
        int c = tid + j * 128;
        if (c < D) out[c] = acc[j];
    }
}

// ================= conversions / utility =================
__global__ void tconv(const float* __restrict__ src, int ldSrc,
                      __nv_bfloat16* __restrict__ dhi, __nv_bfloat16* __restrict__ dlo,
                      int ldDst, int rowOff)
{
    __shared__ float t[32][33];
    int rb = blockIdx.y * 32, cb = blockIdx.x * 32;
    int tx = threadIdx.x, ty = threadIdx.y;
    #pragma unroll
    for (int i = 0; i < 4; i++)
        t[ty + 8 * i][tx] = src[(size_t)(rb + ty + 8 * i) * ldSrc + cb + tx];
    __syncthreads();
    #pragma unroll
    for (int i = 0; i < 4; i++) {
        int c = cb + ty + 8 * i;
        float v = t[tx][ty + 8 * i];
        __nv_bfloat16 h = __float2bfloat16_rn(v);
        size_t o = (size_t)(c + rowOff) * ldDst + rb + tx;
        dhi[o] = h;
        dlo[o] = __float2bfloat16_rn(v - __bfloat162float(h));
    }
}
__global__ void zero_kernel(float* p, int n) {
    int i = blockIdx.x * blockDim.x + threadIdx.x;
    int stride = gridDim.x * blockDim.x;
    float4* p4 = (float4*)p;
    int n4 = n >> 2;
    for (int j = i; j < n4; j += stride) p4[j] = make_float4(0.f, 0.f, 0.f, 0.f);
}
__global__ void relu_kernel(const float* __restrict__ z, float* __restrict__ emb, int n) {
    int i = blockIdx.x * blockDim.x + threadIdx.x;
    if (i < n) emb[i] = fmaxf(z[i], 0.f);
}
__global__ void copy_z_kernel(const float* __restrict__ Z, float* __restrict__ out) {
    int i = blockIdx.x * blockDim.x + threadIdx.x;
    int n = i >> 6, c = i & 63;
    out[i] = Z[n * 128 + c];
}

// ================= readout =================
__global__ void rowsum_kernel(const float* __restrict__ gnm, float* rs)
{
    int warp = threadIdx.x >> 5, lane = threadIdx.x & 31;
    int row = blockIdx.x * 8 + warp;
    const float4* p = (const float4*)(gnm + (size_t)row * NN);
    float s = 0.f;
    for (int i = lane; i < NN / 4; i += 32) { float4 v = p[i]; s += (v.x + v.y) + (v.z + v.w); }
    #pragma unroll
    for (int o = 16; o; o >>= 1) s += __shfl_xor_sync(0xffffffffu, s, o);
    if (lane == 0) rs[row] = s;
}
__global__ void readout_g(const float* __restrict__ VS, const float* __restrict__ rs,
                          float* __restrict__ G)
{
    int b = blockIdx.y;
    int warp = threadIdx.x >> 5, lane = threadIdx.x & 31;
    int n = blockIdx.x * 8 + warp;
    const float* vs = VS + (size_t)n * 128 + b * 64;
    float* g = G + (size_t)b * 262144 + (size_t)n * 64;
    float inv = 1.f / rs[n];
    float v0 = vs[lane] * inv;
    float v1 = vs[lane + 32] * inv;
    float ss = v0 * v0 + v1 * v1;
    #pragma unroll
    for (int o = 16; o; o >>= 1) ss += __shfl_xor_sync(0xffffffffu, ss, o);
    float nrm = fmaxf(sqrtf(ss), 1e-12f);
    g[lane]      = sigmoidf_(v0 / nrm);
    g[lane + 32] = sigmoidf_(v1 / nrm);
}

// ================= bilinear =================
__global__ void bilinear_kernel(const float* __restrict__ EMB,
                                const float* __restrict__ G,
                                const float* __restrict__ Wb, const float* __restrict__ bb,
                                float* ret, float* reta)
{
    __shared__ float sW[64 * 65];
    __shared__ float sg[8][64];
    __shared__ float sga[8][64];
    for (int i = threadIdx.x; i < 64 * 64; i += blockDim.x)
        sW[(i >> 6) * 65 + (i & 63)] = Wb[i];
    int warp = threadIdx.x >> 5, lane = threadIdx.x & 31;
    int n = blockIdx.x * 8 + warp;
    sg[warp][lane]       = G[(size_t)n * 64 + lane];
    sg[warp][lane + 32]  = G[(size_t)n * 64 + lane + 32];
    sga[warp][lane]      = G[262144 + (size_t)n * 64 + lane];
    sga[warp][lane + 32] = G[262144 + (size_t)n * 64 + lane + 32];
    __syncthreads();
    float wcf0 = 0.f, wcf1 = 0.f, wca0 = 0.f, wca1 = 0.f;
    #pragma unroll 8
    for (int k2 = 0; k2 < 64; k2++) {
        float w0 = sW[lane * 65 + k2];
        float w1 = sW[(lane + 32) * 65 + k2];
        float gv = sg[warp][k2], gav = sga[warp][k2];
        wcf0 = fmaf(w0, gv, wcf0);  wcf1 = fmaf(w1, gv, wcf1);
        wca0 = fmaf(w0, gav, wca0); wca1 = fmaf(w1, gav, wca1);
    }
    float e0 = EMB[(size_t)n * 128 + lane],      e1 = EMB[(size_t)n * 128 + lane + 32];
    float a0 = EMB[(size_t)n * 128 + 64 + lane], a1 = EMB[(size_t)n * 128 + 64 + lane + 32];
    float d1 = e0 * wcf0 + e1 * wcf1;
    float d2 = a0 * wcf0 + a1 * wcf1;
    float d3 = a0 * wca0 + a1 * wca1;
    float d4 = e0 * wca0 + e1 * wca1;
    #pragma unroll
    for (int o = 16; o; o >>= 1) {
        d1 += __shfl_xor_sync(0xffffffffu, d1, o);
        d2 += __shfl_xor_sync(0xffffffffu, d2, o);
        d3 += __shfl_xor_sync(0xffffffffu, d3, o);
        d4 += __shfl_xor_sync(0xffffffffu, d4, o);
    }
    if (lane == 0) {
        float bias = bb[0];
        ret[n * 2 + 0]  = sigmoidf_(d1 + bias);
        ret[n * 2 + 1]  = sigmoidf_(d2 + bias);
        reta[n * 2 + 0] = sigmoidf_(d3 + bias);
        reta[n * 2 + 1] = sigmoidf_(d4 + bias);
    }
}

// ================= launch =================
extern "C" void kernel_launch(void* const* d_in, const int* in_sizes, int n_in,
                              void* d_out, int out_size)
{
    const float* feat  = (const float*)d_in[0];
    const float* feata = (const float*)d_in[1];
    const float* adj   = (const float*)d_in[2];
    const float* gn    = (const float*)d_in[3];
    const float* Wl1   = (const float*)d_in[4];
    const float* Wr1   = (const float*)d_in[5];
    const float* att1  = (const float*)d_in[6];
    const float* Wl2   = (const float*)d_in[7];
    const float* Wr2   = (const float*)d_in[8];
    const float* att2  = (const float*)d_in[9];
    const float* Wb    = (const float*)d_in[10];
    const float* bb    = (const float*)d_in[11];
    const int*   src   = (const int*)d_in[12];
    const int*   dst   = (const int*)d_in[13];
    float* out = (float*)d_out;

    float* sc = nullptr;
    __nv_bfloat16* bs = nullptr;
    int* is = nullptr;
    cudaGetSymbolAddress((void**)&sc, g_fscratch);
    cudaGetSymbolAddress((void**)&bs, g_bscratch);
    cudaGetSymbolAddress((void**)&is, g_iscratch);
    cudaFuncSetAttribute(mma_gemm_f32, cudaFuncAttributeMaxDynamicSharedMemorySize, 2 * STG4);

    dim3 tb(32, 8);

    // zero split-K accumulators
    zero_kernel<<<512, 256>>>(sc, 1572864);
    zero_kernel<<<256, 256>>>(sc + OFF_VS, 524288);

    // CSR build (deterministic)
    hist_k<<<256, 256>>>(dst, is + I_HIST);
    scan_tile_k<<<128, 256>>>(is + I_HIST, is + I_HISTT, is + I_CNT);
    scan_total_k<<<1, 1024>>>(is + I_CNT, is + I_BASE);
    scatter_k<<<256, 256>>>(src, dst, is + I_HISTT, is + I_BASE, is + I_SSRC);

    // weight transposes
    tconv<<<dim3(2, 16), tb>>>(Wl1, 64, bs + B_W1T_HI, bs + B_W1T_LO, 512, 0);
    tconv<<<dim3(2, 16), tb>>>(Wr1, 64, bs + B_W1T_HI, bs + B_W1T_LO, 512, 64);
    tconv<<<dim3(16, 2), tb>>>(Wl2, 512, bs + B_W2T_HI, bs + B_W2T_LO, 64, 0);
    tconv<<<dim3(16, 2), tb>>>(Wr2, 512, bs + B_W2T_HI, bs + B_W2T_LO, 64, 512);

    // GEMM1: X1[b] = feat_b @ [Wl1|Wr1]  (M=4096,N=128,K=512; split-K=4 atomic)
    mma_gemm_f32<<<dim3(32, 1, 4), 256, 2 * STG4>>>(
        feat, 512, bs + B_W1T_HI, bs + B_W1T_LO, 512, sc + OFF_X1, 128, 512, 128, 1, 0);
    mma_gemm_f32<<<dim3(32, 1, 4), 256, 2 * STG4>>>(
        feata, 512, bs + B_W1T_HI, bs + B_W1T_LO, 512, sc + OFF_X1 + 524288, 128, 512, 128, 1, 0);

    // GAT layer 1 (fused, batch 2)
    gat_fused<64><<<dim3(4096, 2), 128>>>(sc + OFF_X1, 128, 64, att1,
        is + I_BASE, is + I_SSRC, sc + OFF_E1, sc + OFF_AGG1, 64, 524288, 65536, 262144);

    // transpose agg1 -> A1T [128][4096]
    tconv<<<dim3(2, 128), tb>>>(sc + OFF_AGG1,          64, bs + B_A1T_HI, bs + B_A1T_LO, 4096, 0);
    tconv<<<dim3(2, 128), tb>>>(sc + OFF_AGG1 + 262144, 64, bs + B_A1T_HI, bs + B_A1T_LO, 4096, 64);

    // GEMM2: Z = adj @ [agg1_f|agg1_a]  (M=4096,N=128,K=4096; split-K=4 atomic)
    mma_gemm_f32<<<dim3(32, 1, 4), 256, 2 * STG4>>>(
        adj, 4096, bs + B_A1T_HI, bs + B_A1T_LO, 4096, sc + OFF_Z, 128, 4096, 1024, 1, 0);

    copy_z_kernel<<<1024, 256>>>(sc + OFF_Z, out);
    relu_kernel<<<2048, 256>>>(sc + OFF_Z, sc + OFF_EMB, 524288);

    // GEMM3: X2 = z @ [Wl2|Wr2]  (M=4096,N=1024,K=64)
    mma_gemm_f32<<<dim3(32, 8, 1), 256, 2 * STG4>>>(
        sc + OFF_Z, 128, bs + B_W2T_HI, bs + B_W2T_LO, 64, sc + OFF_X2, 1024, 64, 64, 0, 0);

    // GAT layer 2 (fused)
    gat_fused<512><<<dim3(4096, 1), 128>>>(sc + OFF_X2, 1024, 512, att2,
        is + I_BASE, is + I_SSRC, sc + OFF_E2, sc + OFF_AGG2, 512, 0, 0, 0);

    // transpose agg2 -> A2T [512][4096]
    tconv<<<dim3(16, 128), tb>>>(sc + OFF_AGG2, 512, bs + B_A2T_HI, bs + B_A2T_LO, 4096, 0);

    // GEMM4: h = adj @ agg2  (M=4096,N=512,K=4096) -> out directly
    mma_gemm_f32<<<dim3(32, 4, 1), 256, 2 * STG4>>>(
        adj, 4096, bs + B_A2T_HI, bs + B_A2T_LO, 4096, out + 262144, 512, 4096, 4096, 0, 0);

    // transpose emb -> EMBT [128][4096]
    tconv<<<dim3(2, 128), tb>>>(sc + OFF_EMB,      128, bs + B_EMBT_HI, bs + B_EMBT_LO, 4096, 0);
    tconv<<<dim3(2, 128), tb>>>(sc + OFF_EMB + 64, 128, bs + B_EMBT_HI, bs + B_EMBT_LO, 4096, 64);

    // GEMM5: VS = gn @ [emb|emb_a]  (gn exact in bf16 -> 2-pass, aExact=1)
    mma_gemm_f32<<<dim3(32, 1, 4), 256, 2 * STG4>>>(
        gn, 4096, bs + B_EMBT_HI, bs + B_EMBT_LO, 4096, sc + OFF_VS, 128, 4096, 1024, 1, 1);

    // readout + bilinear
    rowsum_kernel<<<512, 256>>>(gn, sc + OFF_RS);
    readout_g<<<dim3(512, 2), 256>>>(sc + OFF_VS, sc + OFF_RS, sc + OFF_G);
    bilinear_kernel<<<512, 256>>>(sc + OFF_EMB, sc + OFF_G, Wb, bb,
                                  out + 2359296, out + 2367488);
}